// round 1
// baseline (speedup 1.0000x reference)
#include <cuda_runtime.h>
#include <math.h>

// ---------------- scratch (allocation-free: __device__ globals) ----------------
__device__ float g_buf0[32u * 32 * 128 * 128];   // 64 MB ping
__device__ float g_buf1[32u * 32 * 128 * 128];   // 64 MB pong
__device__ float g_S[4096];
__device__ float g_Sh[4096];
__device__ float g_Sw[4096];

__device__ __forceinline__ float activate(float v, int act) {
    switch (act) {
        case 1: return v > 0.f ? v : 0.2f * v;                          // leaky 0.2
        case 2: return v > 0.f ? v : 0.f;                               // relu
        case 3: return fmaxf(v, 0.f) + log1pf(expf(-fabsf(v)));         // softplus
        default: return v;
    }
}

// ---------------- stride-1 3x3 SAME conv (pad 1,1) ----------------
// block: 16x16 out tile x OCB out channels. thread: 2x2 pixels x 8 oc.
template <int OCB>
__global__ void __launch_bounds__(64 * (OCB / 8)) conv_s1(
    const float* __restrict__ in, const float* __restrict__ wgt,
    const float* __restrict__ bias, float* __restrict__ out,
    int C, int OC, int H, int W, int act)
{
    constexpr int NT = 64 * (OCB / 8);
    const int tilesX = W >> 4;
    const int x0 = (blockIdx.x % tilesX) << 4;
    const int y0 = (blockIdx.x / tilesX) << 4;
    const int oc0 = blockIdx.y * OCB;
    const int b = blockIdx.z;

    __shared__ float s_in[18 * 18];
    __shared__ float s_w[OCB * 9];

    const int tid = threadIdx.x;
    const int g = tid >> 6;
    const int sp = tid & 63;
    const int ty = sp >> 3, tx = sp & 7;

    float acc[8][4];
#pragma unroll
    for (int o = 0; o < 8; o++)
#pragma unroll
        for (int p = 0; p < 4; p++) acc[o][p] = 0.f;

    const float* inb = in + (size_t)b * C * H * W;
    const float* wb = wgt + (size_t)oc0 * C * 9;

    for (int ic = 0; ic < C; ic++) {
        const float* inc = inb + (size_t)ic * H * W;
        for (int i = tid; i < 18 * 18; i += NT) {
            int r = i / 18, c = i - r * 18;
            int iy = y0 - 1 + r, ix = x0 - 1 + c;
            float v = 0.f;
            if ((unsigned)iy < (unsigned)H && (unsigned)ix < (unsigned)W)
                v = inc[(size_t)iy * W + ix];
            s_in[i] = v;
        }
        for (int i = tid; i < OCB * 9; i += NT) {
            int o = i / 9, j = i - o * 9;
            s_w[i] = wb[((size_t)o * C + ic) * 9 + j];
        }
        __syncthreads();

        float r_in[4][4];
#pragma unroll
        for (int r = 0; r < 4; r++)
#pragma unroll
            for (int c = 0; c < 4; c++)
                r_in[r][c] = s_in[(2 * ty + r) * 18 + 2 * tx + c];

#pragma unroll
        for (int o = 0; o < 8; o++) {
            const float* w9 = &s_w[(g * 8 + o) * 9];
            float w[9];
#pragma unroll
            for (int j = 0; j < 9; j++) w[j] = w9[j];
#pragma unroll
            for (int dy = 0; dy < 2; dy++)
#pragma unroll
                for (int dx = 0; dx < 2; dx++) {
                    float s = acc[o][dy * 2 + dx];
#pragma unroll
                    for (int ky = 0; ky < 3; ky++)
#pragma unroll
                        for (int kx = 0; kx < 3; kx++)
                            s += w[ky * 3 + kx] * r_in[dy + ky][dx + kx];
                    acc[o][dy * 2 + dx] = s;
                }
        }
        __syncthreads();
    }

#pragma unroll
    for (int o = 0; o < 8; o++) {
        int oc = oc0 + g * 8 + o;
        float bv = bias[oc];
        float* ob = out + (((size_t)b * OC + oc) * H + y0) * (size_t)W + x0;
#pragma unroll
        for (int dy = 0; dy < 2; dy++)
#pragma unroll
            for (int dx = 0; dx < 2; dx++)
                ob[(size_t)(2 * ty + dy) * W + 2 * tx + dx] =
                    activate(acc[o][dy * 2 + dx] + bv, act);
    }
}

// ---------------- stride-2 3x3 SAME conv (JAX: pad lo=0, hi=1) ----------------
// block: 16x16 out tile x 32 oc. thread: 2x2 out pixels x 8 oc.
__global__ void __launch_bounds__(256) conv_s2(
    const float* __restrict__ in, const float* __restrict__ wgt,
    const float* __restrict__ bias, float* __restrict__ out,
    int C, int OC, int Hout, int Wout, int act)
{
    const int Hin = Hout * 2, Win = Wout * 2;
    const int tilesX = Wout >> 4;
    const int x0 = (blockIdx.x % tilesX) << 4;
    const int y0 = (blockIdx.x / tilesX) << 4;
    const int oc0 = blockIdx.y * 32;
    const int b = blockIdx.z;

    __shared__ float s_in[33 * 33];
    __shared__ float s_w[32 * 9];

    const int tid = threadIdx.x;
    const int g = tid >> 6;
    const int sp = tid & 63;
    const int ty = sp >> 3, tx = sp & 7;

    float acc[8][4];
#pragma unroll
    for (int o = 0; o < 8; o++)
#pragma unroll
        for (int p = 0; p < 4; p++) acc[o][p] = 0.f;

    const float* inb = in + (size_t)b * C * Hin * Win;
    const float* wb = wgt + (size_t)oc0 * C * 9;

    for (int ic = 0; ic < C; ic++) {
        const float* inc = inb + (size_t)ic * Hin * Win;
        for (int i = tid; i < 33 * 33; i += 256) {
            int r = i / 33, c = i - r * 33;
            int iy = 2 * y0 + r, ix = 2 * x0 + c;
            float v = 0.f;
            if (iy < Hin && ix < Win) v = inc[(size_t)iy * Win + ix];
            s_in[i] = v;
        }
        for (int i = tid; i < 32 * 9; i += 256) {
            int o = i / 9, j = i - o * 9;
            s_w[i] = wb[((size_t)o * C + ic) * 9 + j];
        }
        __syncthreads();

        float r_in[5][5];
#pragma unroll
        for (int r = 0; r < 5; r++)
#pragma unroll
            for (int c = 0; c < 5; c++)
                r_in[r][c] = s_in[(4 * ty + r) * 33 + 4 * tx + c];

#pragma unroll
        for (int o = 0; o < 8; o++) {
            const float* w9 = &s_w[(g * 8 + o) * 9];
            float w[9];
#pragma unroll
            for (int j = 0; j < 9; j++) w[j] = w9[j];
#pragma unroll
            for (int dy = 0; dy < 2; dy++)
#pragma unroll
                for (int dx = 0; dx < 2; dx++) {
                    float s = acc[o][dy * 2 + dx];
#pragma unroll
                    for (int ky = 0; ky < 3; ky++)
#pragma unroll
                        for (int kx = 0; kx < 3; kx++)
                            s += w[ky * 3 + kx] * r_in[2 * dy + ky][2 * dx + kx];
                    acc[o][dy * 2 + dx] = s;
                }
        }
        __syncthreads();
    }

#pragma unroll
    for (int o = 0; o < 8; o++) {
        int oc = oc0 + g * 8 + o;
        float bv = bias[oc];
        float* ob = out + (((size_t)b * OC + oc) * Hout + y0) * (size_t)Wout + x0;
#pragma unroll
        for (int dy = 0; dy < 2; dy++)
#pragma unroll
            for (int dx = 0; dx < 2; dx++)
                ob[(size_t)(2 * ty + dy) * Wout + 2 * tx + dx] =
                    activate(acc[o][dy * 2 + dx] + bv, act);
    }
}

// ---------------- transposed conv 3x3 stride-2 SAME (JAX conv_transpose) -------
// pad_a=2 => out[y] taps: y even -> W[0]*X[y/2-1] + W[2]*X[y/2]; y odd -> W[1]*X[(y-1)/2]
// block: 32x32 out tile x 16 oc. thread: 4x4 out pixels x 4 oc. relu applied.
__global__ void __launch_bounds__(256) tconv_s2(
    const float* __restrict__ in, const float* __restrict__ wgt,
    const float* __restrict__ bias, float* __restrict__ out,
    int C, int OC, int Hout, int Wout)
{
    const int Hin = Hout >> 1, Win = Wout >> 1;
    const int tilesX = Wout >> 5;
    const int x0 = (blockIdx.x % tilesX) << 5;
    const int y0 = (blockIdx.x / tilesX) << 5;
    const int oc0 = blockIdx.y * 16;
    const int b = blockIdx.z;

    __shared__ float s_in[17 * 17];
    __shared__ float s_w[16 * 9];

    const int tid = threadIdx.x;
    const int g = tid >> 6;            // 4 oc-groups of 4
    const int sp = tid & 63;
    const int ty = sp >> 3, tx = sp & 7;
    const int Y0 = y0 >> 1, X0 = x0 >> 1;

    float acc[4][16];
#pragma unroll
    for (int o = 0; o < 4; o++)
#pragma unroll
        for (int p = 0; p < 16; p++) acc[o][p] = 0.f;

    const float* inb = in + (size_t)b * C * Hin * Win;
    const float* wb = wgt + (size_t)oc0 * C * 9;

    for (int ic = 0; ic < C; ic++) {
        const float* inc = inb + (size_t)ic * Hin * Win;
        for (int i = tid; i < 17 * 17; i += 256) {
            int r = i / 17, c = i - r * 17;
            int iy = Y0 - 1 + r, ix = X0 - 1 + c;
            float v = 0.f;
            if ((unsigned)iy < (unsigned)Hin && (unsigned)ix < (unsigned)Win)
                v = inc[(size_t)iy * Win + ix];
            s_in[i] = v;
        }
        for (int i = tid; i < 16 * 9; i += 256) {
            int o = i / 9, j = i - o * 9;
            s_w[i] = wb[((size_t)o * C + ic) * 9 + j];
        }
        __syncthreads();

        float r_in[3][3];
#pragma unroll
        for (int p = 0; p < 3; p++)
#pragma unroll
            for (int q = 0; q < 3; q++)
                r_in[p][q] = s_in[(2 * ty + p) * 17 + 2 * tx + q];

#pragma unroll
        for (int o = 0; o < 4; o++) {
            const float* w9 = &s_w[(g * 4 + o) * 9];
            float w[9];
#pragma unroll
            for (int j = 0; j < 9; j++) w[j] = w9[j];
#pragma unroll
            for (int dy = 0; dy < 4; dy++)
#pragma unroll
                for (int dx = 0; dx < 4; dx++) {
                    float s = acc[o][dy * 4 + dx];
#pragma unroll
                    for (int ky = 0; ky < 3; ky++) {
                        if (((dy + ky) & 1) == 0) {
#pragma unroll
                            for (int kx = 0; kx < 3; kx++) {
                                if (((dx + kx) & 1) == 0)
                                    s += w[ky * 3 + kx] *
                                         r_in[(dy + ky) >> 1][(dx + kx) >> 1];
                            }
                        }
                    }
                    acc[o][dy * 4 + dx] = s;
                }
        }
        __syncthreads();
    }

#pragma unroll
    for (int o = 0; o < 4; o++) {
        int oc = oc0 + g * 4 + o;
        float bv = bias[oc];
        float* ob = out + (((size_t)b * OC + oc) * Hout + y0 + 4 * ty) * (size_t)Wout
                        + x0 + 4 * tx;
#pragma unroll
        for (int dy = 0; dy < 4; dy++)
#pragma unroll
            for (int dx = 0; dx < 4; dx++) {
                float v = acc[o][dy * 4 + dx] + bv;
                ob[(size_t)dy * Wout + dx] = v > 0.f ? v : 0.f;
            }
    }
}

// ---------------- keypoint bottleneck ----------------
// stats: per (b,k) over 16x16: S = sum R, Sh = sum R*h, Sw = sum R*w
__global__ void bn_stats(const float* __restrict__ R, float* __restrict__ S,
                         float* __restrict__ Sh, float* __restrict__ Sw)
{
    int bk = blockIdx.x;
    int t = threadIdx.x;
    float v = R[(size_t)bk * 256 + t];
    float a = v;
    float bsum = v * (float)(t >> 4);
    float c = v * (float)(t & 15);
#pragma unroll
    for (int off = 16; off > 0; off >>= 1) {
        a += __shfl_down_sync(0xffffffffu, a, off);
        bsum += __shfl_down_sync(0xffffffffu, bsum, off);
        c += __shfl_down_sync(0xffffffffu, c, off);
    }
    __shared__ float sa[8], sb[8], sc[8];
    int wid = t >> 5;
    if ((t & 31) == 0) { sa[wid] = a; sb[wid] = bsum; sc[wid] = c; }
    __syncthreads();
    if (t == 0) {
        float ta = 0.f, tb = 0.f, tc = 0.f;
        for (int i = 0; i < 8; i++) { ta += sa[i]; tb += sb[i]; tc += sc[i]; }
        S[bk] = ta; Sh[bk] = tb; Sw[bk] = tc;
    }
}

// maps: mu * exp(-0.5*((h-c0)^2+(w-c1)^2)); denom = original sum of LAST map (k=127)
__global__ void bn_maps(const float* __restrict__ S, const float* __restrict__ Sh,
                        const float* __restrict__ Sw, float* __restrict__ maps)
{
    int bk = blockIdx.x;
    int b = bk >> 7;
    float s = S[bk];
    float denom = S[(b << 7) | 127];
    float mu = s * (1.f / 256.f);
    float inv = 1.f / denom;
    float c0 = Sh[bk] * inv;
    float c1 = Sw[bk] * inv;
    int t = threadIdx.x;
    float h = (float)(t >> 4), w = (float)(t & 15);
    float dh = h - c0, dw = w - c1;
    maps[(size_t)bk * 256 + t] = mu * expf(-0.5f * (dh * dh + dw * dw));
}

// ---------------- launch ----------------
extern "C" void kernel_launch(void* const* d_in, const int* in_sizes, int n_in,
                              void* d_out, int out_size)
{
    (void)in_sizes; (void)n_in; (void)out_size;
    const float* x = (const float*)d_in[0];
    const float* ew[7]; const float* eb[7];
    for (int j = 0; j < 7; j++) {
        ew[j] = (const float*)d_in[1 + 2 * j];
        eb[j] = (const float*)d_in[2 + 2 * j];
    }
    const float* dw[6]; const float* db[6];
    for (int j = 0; j < 6; j++) {
        dw[j] = (const float*)d_in[15 + 2 * j];
        db[j] = (const float*)d_in[16 + 2 * j];
    }
    float* out = (float*)d_out;

    float *buf0, *buf1, *S, *Sh, *Sw;
    cudaGetSymbolAddress((void**)&buf0, g_buf0);
    cudaGetSymbolAddress((void**)&buf1, g_buf1);
    cudaGetSymbolAddress((void**)&S, g_S);
    cudaGetSymbolAddress((void**)&Sh, g_Sh);
    cudaGetSymbolAddress((void**)&Sw, g_Sw);

    const int B = 32;
    // ---- encoder ----
    conv_s1<32><<<dim3(64, 1, B), 256>>>(x,    ew[0], eb[0], buf0, 3,   32, 128, 128, 0);
    conv_s1<32><<<dim3(64, 1, B), 256>>>(buf0, ew[1], eb[1], buf1, 32,  32, 128, 128, 0);
    conv_s2    <<<dim3(16, 2, B), 256>>>(buf1, ew[2], eb[2], buf0, 32,  64, 64, 64, 1);
    conv_s1<32><<<dim3(16, 2, B), 256>>>(buf0, ew[3], eb[3], buf1, 64,  64, 64, 64, 1);
    conv_s2    <<<dim3(4, 4, B),  256>>>(buf1, ew[4], eb[4], buf0, 64, 128, 32, 32, 1);
    conv_s1<32><<<dim3(4, 4, B),  256>>>(buf0, ew[5], eb[5], buf1, 128, 128, 32, 32, 1);
    conv_s2    <<<dim3(1, 4, B),  256>>>(buf1, ew[6], eb[6], buf0, 128, 128, 16, 16, 3);
    // ---- keypoint bottleneck ----
    bn_stats<<<4096, 256>>>(buf0, S, Sh, Sw);
    bn_maps <<<4096, 256>>>(S, Sh, Sw, buf1);
    // ---- decoder ----
    tconv_s2   <<<dim3(1, 4, B),  256>>>(buf1, dw[0], db[0], buf0, 128, 64, 32, 32);
    conv_s1<32><<<dim3(4, 2, B),  256>>>(buf0, dw[1], db[1], buf1, 64,  64, 32, 32, 2);
    tconv_s2   <<<dim3(4, 2, B),  256>>>(buf1, dw[2], db[2], buf0, 64,  32, 64, 64);
    conv_s1<32><<<dim3(16, 1, B), 256>>>(buf0, dw[3], db[3], buf1, 32,  32, 64, 64, 2);
    tconv_s2   <<<dim3(16, 1, B), 256>>>(buf1, dw[4], db[4], buf0, 32,  16, 128, 128);
    conv_s1<16><<<dim3(64, 1, B), 128>>>(buf0, dw[5], db[5], out,  16,  16, 128, 128, 2);
}

// round 2
// speedup vs baseline: 1.5662x; 1.5662x over previous
#include <cuda_runtime.h>
#include <math.h>

// ---------------- scratch (allocation-free: __device__ globals) ----------------
__device__ float g_buf0[32u * 32 * 128 * 128];   // 64 MB ping
__device__ float g_buf1[32u * 32 * 128 * 128];   // 64 MB pong
__device__ float g_S[4096];
__device__ float g_Sh[4096];
__device__ float g_Sw[4096];

__device__ __forceinline__ float activate(float v, int act) {
    switch (act) {
        case 1: return v > 0.f ? v : 0.2f * v;                          // leaky 0.2
        case 2: return v > 0.f ? v : 0.f;                               // relu
        case 3: return fmaxf(v, 0.f) + log1pf(expf(-fabsf(v)));         // softplus
        default: return v;
    }
}

__device__ __forceinline__ void cp_async4(void* sdst, const void* gsrc, bool pred) {
    unsigned saddr = (unsigned)__cvta_generic_to_shared(sdst);
    int sz = pred ? 4 : 0;
    asm volatile("cp.async.ca.shared.global [%0], [%1], 4, %2;\n"
                 :: "r"(saddr), "l"(gsrc), "r"(sz));
}
__device__ __forceinline__ void cp_commit() { asm volatile("cp.async.commit_group;\n"); }
__device__ __forceinline__ void cp_wait0() { asm volatile("cp.async.wait_group 0;\n"); }

// =====================================================================
// stride-1 3x3 SAME conv. block: 16x16 out tile x OCB oc.
// thread: 2x2 px x 8 oc. ICB=4 channel stages, cp.async double buffered.
// =====================================================================
template <int OCB>
__global__ void __launch_bounds__(64 * (OCB / 8), 768 / (64 * (OCB / 8))) conv_s1(
    const float* __restrict__ in, const float* __restrict__ wgt,
    const float* __restrict__ bias, float* __restrict__ out,
    int C, int OC, int H, int W, int act)
{
    constexpr int NT = 64 * (OCB / 8);
    constexpr int ICB = 4;
    constexpr int SIN = 18 * 18;  // 324 (even -> float2-safe)

    const int tilesX = W >> 4;
    const int x0 = (blockIdx.x % tilesX) << 4;
    const int y0 = (blockIdx.x / tilesX) << 4;
    const int oc0 = blockIdx.y * OCB;
    const int b = blockIdx.z;

    __shared__ __align__(16) float s_in[2][ICB][SIN];
    __shared__ __align__(16) float s_w[2][ICB][OCB * 12];

    const int tid = threadIdx.x;
    const int g = tid >> 6;
    const int sp = tid & 63;
    const int ty = sp >> 3, tx = sp & 7;

    float acc[8][4];
#pragma unroll
    for (int o = 0; o < 8; o++)
#pragma unroll
        for (int p = 0; p < 4; p++) acc[o][p] = 0.f;

    const float* inb = in + (size_t)b * C * H * W;
    const float* wb = wgt + (size_t)oc0 * C * 9;

    auto stage_copy = [&](int buf, int ic0, int cnt) {
        const float* ins = inb + (size_t)ic0 * H * W;
        for (int i = tid; i < cnt * SIN; i += NT) {
            int ch = i / SIN, r2 = i - ch * SIN;
            int r = r2 / 18, c2 = r2 - r * 18;
            int iy = y0 - 1 + r, ix = x0 - 1 + c2;
            bool p = (unsigned)iy < (unsigned)H && (unsigned)ix < (unsigned)W;
            cp_async4(&s_in[buf][ch][r2], ins + (size_t)ch * H * W + (size_t)iy * W + ix, p);
        }
        for (int i = tid; i < cnt * OCB * 9; i += NT) {
            int ch = i / (OCB * 9), r2 = i - ch * (OCB * 9);
            int o = r2 / 9, j2 = r2 - o * 9;
            cp_async4(&s_w[buf][ch][o * 12 + j2],
                      wb + ((size_t)o * C + ic0 + ch) * 9 + j2, true);
        }
    };

    auto compute_ch = [&](int buf, int ch) {
        float rr[4][4];
#pragma unroll
        for (int r = 0; r < 4; r++) {
            const float* p = &s_in[buf][ch][(2 * ty + r) * 18 + 2 * tx];
            float2 u = *(const float2*)p;
            float2 v = *(const float2*)(p + 2);
            rr[r][0] = u.x; rr[r][1] = u.y; rr[r][2] = v.x; rr[r][3] = v.y;
        }
#pragma unroll
        for (int o = 0; o < 8; o++) {
            const float4* wp = (const float4*)&s_w[buf][ch][(g * 8 + o) * 12];
            float4 wa = wp[0];
            float4 wc = wp[1];
            float w8 = ((const float*)wp)[8];
            // w0..w8 = wa.x wa.y wa.z wa.w wc.x wc.y wc.z wc.w w8
#pragma unroll
            for (int dy = 0; dy < 2; dy++)
#pragma unroll
                for (int dx = 0; dx < 2; dx++) {
                    float s = acc[o][dy * 2 + dx];
                    s += wa.x * rr[dy + 0][dx + 0];
                    s += wa.y * rr[dy + 0][dx + 1];
                    s += wa.z * rr[dy + 0][dx + 2];
                    s += wa.w * rr[dy + 1][dx + 0];
                    s += wc.x * rr[dy + 1][dx + 1];
                    s += wc.y * rr[dy + 1][dx + 2];
                    s += wc.z * rr[dy + 2][dx + 0];
                    s += wc.w * rr[dy + 2][dx + 1];
                    s += w8   * rr[dy + 2][dx + 2];
                    acc[o][dy * 2 + dx] = s;
                }
        }
    };

    const int nst = (C + ICB - 1) / ICB;
    stage_copy(0, 0, C < ICB ? C : ICB);
    cp_commit();
    for (int s = 0; s < nst; s++) {
        int buf = s & 1;
        cp_wait0();
        __syncthreads();
        int icn = (s + 1) * ICB;
        if (icn < C) {
            int cn = C - icn; if (cn > ICB) cn = ICB;
            stage_copy(buf ^ 1, icn, cn);
        }
        cp_commit();
        int cnt = C - s * ICB; if (cnt > ICB) cnt = ICB;
        if (cnt == ICB) {
#pragma unroll
            for (int j = 0; j < ICB; j++) compute_ch(buf, j);
        } else {
            for (int j = 0; j < cnt; j++) compute_ch(buf, j);
        }
    }

#pragma unroll
    for (int o = 0; o < 8; o++) {
        int oc = oc0 + g * 8 + o;
        float bv = bias[oc];
        float* ob = out + (((size_t)b * OC + oc) * H + y0) * (size_t)W + x0;
#pragma unroll
        for (int dy = 0; dy < 2; dy++)
#pragma unroll
            for (int dx = 0; dx < 2; dx++)
                ob[(size_t)(2 * ty + dy) * W + 2 * tx + dx] =
                    activate(acc[o][dy * 2 + dx] + bv, act);
    }
}

// =====================================================================
// stride-2 3x3 SAME conv (JAX: pad lo=0, hi=1). block: 16x16 out tile x OCB oc.
// thread: 2x2 out px x 8 oc. ICB=4 stages, cp.async double buffered.
// =====================================================================
template <int OCB>
__global__ void __launch_bounds__(64 * (OCB / 8), 512 / (64 * (OCB / 8))) conv_s2(
    const float* __restrict__ in, const float* __restrict__ wgt,
    const float* __restrict__ bias, float* __restrict__ out,
    int C, int OC, int Hout, int Wout, int act)
{
    constexpr int NT = 64 * (OCB / 8);
    constexpr int ICB = 4;
    constexpr int SIN = 33 * 33;  // 1089

    const int Hin = Hout * 2, Win = Wout * 2;
    const int tilesX = Wout >> 4;
    const int x0 = (blockIdx.x % tilesX) << 4;
    const int y0 = (blockIdx.x / tilesX) << 4;
    const int oc0 = blockIdx.y * OCB;
    const int b = blockIdx.z;

    __shared__ __align__(16) float s_in[2][ICB][SIN + 1];
    __shared__ __align__(16) float s_w[2][ICB][OCB * 12];

    const int tid = threadIdx.x;
    const int g = tid >> 6;
    const int sp = tid & 63;
    const int ty = sp >> 3, tx = sp & 7;

    float acc[8][4];
#pragma unroll
    for (int o = 0; o < 8; o++)
#pragma unroll
        for (int p = 0; p < 4; p++) acc[o][p] = 0.f;

    const float* inb = in + (size_t)b * C * Hin * Win;
    const float* wb = wgt + (size_t)oc0 * C * 9;

    auto stage_copy = [&](int buf, int ic0, int cnt) {
        const float* ins = inb + (size_t)ic0 * Hin * Win;
        for (int i = tid; i < cnt * SIN; i += NT) {
            int ch = i / SIN, r2 = i - ch * SIN;
            int r = r2 / 33, c2 = r2 - r * 33;
            int iy = 2 * y0 + r, ix = 2 * x0 + c2;
            bool p = iy < Hin && ix < Win;
            cp_async4(&s_in[buf][ch][r2], ins + (size_t)ch * Hin * Win + (size_t)iy * Win + ix, p);
        }
        for (int i = tid; i < cnt * OCB * 9; i += NT) {
            int ch = i / (OCB * 9), r2 = i - ch * (OCB * 9);
            int o = r2 / 9, j2 = r2 - o * 9;
            cp_async4(&s_w[buf][ch][o * 12 + j2],
                      wb + ((size_t)o * C + ic0 + ch) * 9 + j2, true);
        }
    };

    auto compute_ch = [&](int buf, int ch) {
        float rr[5][5];
#pragma unroll
        for (int r = 0; r < 5; r++)
#pragma unroll
            for (int c = 0; c < 5; c++)
                rr[r][c] = s_in[buf][ch][(4 * ty + r) * 33 + 4 * tx + c];
#pragma unroll
        for (int o = 0; o < 8; o++) {
            const float4* wp = (const float4*)&s_w[buf][ch][(g * 8 + o) * 12];
            float4 wa = wp[0];
            float4 wc = wp[1];
            float w8 = ((const float*)wp)[8];
#pragma unroll
            for (int dy = 0; dy < 2; dy++)
#pragma unroll
                for (int dx = 0; dx < 2; dx++) {
                    float s = acc[o][dy * 2 + dx];
                    s += wa.x * rr[2 * dy + 0][2 * dx + 0];
                    s += wa.y * rr[2 * dy + 0][2 * dx + 1];
                    s += wa.z * rr[2 * dy + 0][2 * dx + 2];
                    s += wa.w * rr[2 * dy + 1][2 * dx + 0];
                    s += wc.x * rr[2 * dy + 1][2 * dx + 1];
                    s += wc.y * rr[2 * dy + 1][2 * dx + 2];
                    s += wc.z * rr[2 * dy + 2][2 * dx + 0];
                    s += wc.w * rr[2 * dy + 2][2 * dx + 1];
                    s += w8   * rr[2 * dy + 2][2 * dx + 2];
                    acc[o][dy * 2 + dx] = s;
                }
        }
    };

    const int nst = (C + ICB - 1) / ICB;
    stage_copy(0, 0, C < ICB ? C : ICB);
    cp_commit();
    for (int s = 0; s < nst; s++) {
        int buf = s & 1;
        cp_wait0();
        __syncthreads();
        int icn = (s + 1) * ICB;
        if (icn < C) {
            int cn = C - icn; if (cn > ICB) cn = ICB;
            stage_copy(buf ^ 1, icn, cn);
        }
        cp_commit();
        int cnt = C - s * ICB; if (cnt > ICB) cnt = ICB;
        if (cnt == ICB) {
#pragma unroll
            for (int j = 0; j < ICB; j++) compute_ch(buf, j);
        } else {
            for (int j = 0; j < cnt; j++) compute_ch(buf, j);
        }
    }

#pragma unroll
    for (int o = 0; o < 8; o++) {
        int oc = oc0 + g * 8 + o;
        float bv = bias[oc];
        float* ob = out + (((size_t)b * OC + oc) * Hout + y0) * (size_t)Wout + x0;
#pragma unroll
        for (int dy = 0; dy < 2; dy++)
#pragma unroll
            for (int dx = 0; dx < 2; dx++)
                ob[(size_t)(2 * ty + dy) * Wout + 2 * tx + dx] =
                    activate(acc[o][dy * 2 + dx] + bv, act);
    }
}

// =====================================================================
// transposed conv 3x3 stride-2 SAME (JAX conv_transpose, pad_a=2):
// out[y] even: W[0]X[y/2-1] + W[2]X[y/2];  out[y] odd: W[1]X[(y-1)/2]
// block: 16x16 out tile x 16 oc. thread: 2x2 out px x 4 oc. relu epilogue.
// =====================================================================
__global__ void __launch_bounds__(256, 3) tconv_s2(
    const float* __restrict__ in, const float* __restrict__ wgt,
    const float* __restrict__ bias, float* __restrict__ out,
    int C, int OC, int Hout, int Wout)
{
    constexpr int NT = 256;
    constexpr int ICB = 4;
    constexpr int SIN = 9 * 9;  // 81

    const int Hin = Hout >> 1, Win = Wout >> 1;
    const int tilesX = Wout >> 4;
    const int x0 = (blockIdx.x % tilesX) << 4;
    const int y0 = (blockIdx.x / tilesX) << 4;
    const int oc0 = blockIdx.y * 16;
    const int b = blockIdx.z;
    const int Y0 = y0 >> 1, X0 = x0 >> 1;

    __shared__ __align__(16) float s_in[2][ICB][SIN + 3];
    __shared__ __align__(16) float s_w[2][ICB][16 * 12];

    const int tid = threadIdx.x;
    const int g = tid >> 6;            // 4 oc-groups of 4
    const int sp = tid & 63;
    const int ty = sp >> 3, tx = sp & 7;

    float acc[4][4];
#pragma unroll
    for (int o = 0; o < 4; o++)
#pragma unroll
        for (int p = 0; p < 4; p++) acc[o][p] = 0.f;

    const float* inb = in + (size_t)b * C * Hin * Win;
    const float* wb = wgt + (size_t)oc0 * C * 9;

    auto stage_copy = [&](int buf, int ic0, int cnt) {
        const float* ins = inb + (size_t)ic0 * Hin * Win;
        for (int i = tid; i < cnt * SIN; i += NT) {
            int ch = i / SIN, r2 = i - ch * SIN;
            int r = r2 / 9, c2 = r2 - r * 9;
            int iy = Y0 - 1 + r, ix = X0 - 1 + c2;
            bool p = (unsigned)iy < (unsigned)Hin && (unsigned)ix < (unsigned)Win;
            cp_async4(&s_in[buf][ch][r2], ins + (size_t)ch * Hin * Win + (size_t)iy * Win + ix, p);
        }
        for (int i = tid; i < cnt * 16 * 9; i += NT) {
            int ch = i / (16 * 9), r2 = i - ch * (16 * 9);
            int o = r2 / 9, j2 = r2 - o * 9;
            cp_async4(&s_w[buf][ch][o * 12 + j2],
                      wb + ((size_t)o * C + ic0 + ch) * 9 + j2, true);
        }
    };

    auto compute_ch = [&](int buf, int ch) {
        const float* si = s_in[buf][ch];
        float r00 = si[ty * 9 + tx];
        float r01 = si[ty * 9 + tx + 1];
        float r10 = si[(ty + 1) * 9 + tx];
        float r11 = si[(ty + 1) * 9 + tx + 1];
#pragma unroll
        for (int o = 0; o < 4; o++) {
            const float4* wp = (const float4*)&s_w[buf][ch][(g * 4 + o) * 12];
            float4 wa = wp[0];
            float4 wc = wp[1];
            float w8 = ((const float*)wp)[8];
            // (0,0): w0*r00 + w2*r01 + w6*r10 + w8*r11
            acc[o][0] += wa.x * r00 + wa.z * r01 + wc.z * r10 + w8 * r11;
            // (0,1): w1*r01 + w7*r11
            acc[o][1] += wa.y * r01 + wc.w * r11;
            // (1,0): w3*r10 + w5*r11
            acc[o][2] += wa.w * r10 + wc.y * r11;
            // (1,1): w4*r11
            acc[o][3] += wc.x * r11;
        }
    };

    const int nst = (C + ICB - 1) / ICB;
    stage_copy(0, 0, C < ICB ? C : ICB);
    cp_commit();
    for (int s = 0; s < nst; s++) {
        int buf = s & 1;
        cp_wait0();
        __syncthreads();
        int icn = (s + 1) * ICB;
        if (icn < C) {
            int cn = C - icn; if (cn > ICB) cn = ICB;
            stage_copy(buf ^ 1, icn, cn);
        }
        cp_commit();
        int cnt = C - s * ICB; if (cnt > ICB) cnt = ICB;
        if (cnt == ICB) {
#pragma unroll
            for (int j = 0; j < ICB; j++) compute_ch(buf, j);
        } else {
            for (int j = 0; j < cnt; j++) compute_ch(buf, j);
        }
    }

#pragma unroll
    for (int o = 0; o < 4; o++) {
        int oc = oc0 + g * 4 + o;
        float bv = bias[oc];
        float* ob = out + (((size_t)b * OC + oc) * Hout + y0) * (size_t)Wout + x0;
#pragma unroll
        for (int dy = 0; dy < 2; dy++)
#pragma unroll
            for (int dx = 0; dx < 2; dx++) {
                float v = acc[o][dy * 2 + dx] + bv;
                ob[(size_t)(2 * ty + dy) * Wout + 2 * tx + dx] = v > 0.f ? v : 0.f;
            }
    }
}

// ---------------- keypoint bottleneck ----------------
__global__ void bn_stats(const float* __restrict__ R, float* __restrict__ S,
                         float* __restrict__ Sh, float* __restrict__ Sw)
{
    int bk = blockIdx.x;
    int t = threadIdx.x;
    float v = R[(size_t)bk * 256 + t];
    float a = v;
    float bsum = v * (float)(t >> 4);
    float c = v * (float)(t & 15);
#pragma unroll
    for (int off = 16; off > 0; off >>= 1) {
        a += __shfl_down_sync(0xffffffffu, a, off);
        bsum += __shfl_down_sync(0xffffffffu, bsum, off);
        c += __shfl_down_sync(0xffffffffu, c, off);
    }
    __shared__ float sa[8], sb[8], sc[8];
    int wid = t >> 5;
    if ((t & 31) == 0) { sa[wid] = a; sb[wid] = bsum; sc[wid] = c; }
    __syncthreads();
    if (t == 0) {
        float ta = 0.f, tb = 0.f, tc = 0.f;
        for (int i = 0; i < 8; i++) { ta += sa[i]; tb += sb[i]; tc += sc[i]; }
        S[bk] = ta; Sh[bk] = tb; Sw[bk] = tc;
    }
}

__global__ void bn_maps(const float* __restrict__ S, const float* __restrict__ Sh,
                        const float* __restrict__ Sw, float* __restrict__ maps)
{
    int bk = blockIdx.x;
    int b = bk >> 7;
    float s = S[bk];
    float denom = S[(b << 7) | 127];
    float mu = s * (1.f / 256.f);
    float inv = 1.f / denom;
    float c0 = Sh[bk] * inv;
    float c1 = Sw[bk] * inv;
    int t = threadIdx.x;
    float h = (float)(t >> 4), w = (float)(t & 15);
    float dh = h - c0, dw = w - c1;
    maps[(size_t)bk * 256 + t] = mu * expf(-0.5f * (dh * dh + dw * dw));
}

// ---------------- launch ----------------
extern "C" void kernel_launch(void* const* d_in, const int* in_sizes, int n_in,
                              void* d_out, int out_size)
{
    (void)in_sizes; (void)n_in; (void)out_size;
    const float* x = (const float*)d_in[0];
    const float* ew[7]; const float* eb[7];
    for (int j = 0; j < 7; j++) {
        ew[j] = (const float*)d_in[1 + 2 * j];
        eb[j] = (const float*)d_in[2 + 2 * j];
    }
    const float* dw[6]; const float* db[6];
    for (int j = 0; j < 6; j++) {
        dw[j] = (const float*)d_in[15 + 2 * j];
        db[j] = (const float*)d_in[16 + 2 * j];
    }
    float* out = (float*)d_out;

    float *buf0, *buf1, *S, *Sh, *Sw;
    cudaGetSymbolAddress((void**)&buf0, g_buf0);
    cudaGetSymbolAddress((void**)&buf1, g_buf1);
    cudaGetSymbolAddress((void**)&S, g_S);
    cudaGetSymbolAddress((void**)&Sh, g_Sh);
    cudaGetSymbolAddress((void**)&Sw, g_Sw);

    const int B = 32;
    // ---- encoder ----
    conv_s1<32><<<dim3(64, 1, B), 256>>>(x,    ew[0], eb[0], buf0, 3,   32, 128, 128, 0);
    conv_s1<32><<<dim3(64, 1, B), 256>>>(buf0, ew[1], eb[1], buf1, 32,  32, 128, 128, 0);
    conv_s2<32><<<dim3(16, 2, B), 256>>>(buf1, ew[2], eb[2], buf0, 32,  64, 64, 64, 1);
    conv_s1<32><<<dim3(16, 2, B), 256>>>(buf0, ew[3], eb[3], buf1, 64,  64, 64, 64, 1);
    conv_s2<32><<<dim3(4, 4, B),  256>>>(buf1, ew[4], eb[4], buf0, 64, 128, 32, 32, 1);
    conv_s1<32><<<dim3(4, 4, B),  256>>>(buf0, ew[5], eb[5], buf1, 128, 128, 32, 32, 1);
    conv_s2<8> <<<dim3(1, 16, B), 64>>> (buf1, ew[6], eb[6], buf0, 128, 128, 16, 16, 3);
    // ---- keypoint bottleneck ----
    bn_stats<<<4096, 256>>>(buf0, S, Sh, Sw);
    bn_maps <<<4096, 256>>>(S, Sh, Sw, buf1);
    // ---- decoder ----
    tconv_s2   <<<dim3(4, 4, B),  256>>>(buf1, dw[0], db[0], buf0, 128, 64, 32, 32);
    conv_s1<16><<<dim3(4, 4, B),  128>>>(buf0, dw[1], db[1], buf1, 64,  64, 32, 32, 2);
    tconv_s2   <<<dim3(16, 2, B), 256>>>(buf1, dw[2], db[2], buf0, 64,  32, 64, 64);
    conv_s1<16><<<dim3(16, 2, B), 128>>>(buf0, dw[3], db[3], buf1, 32,  32, 64, 64, 2);
    tconv_s2   <<<dim3(64, 1, B), 256>>>(buf1, dw[4], db[4], buf0, 32,  16, 128, 128);
    conv_s1<16><<<dim3(64, 1, B), 128>>>(buf0, dw[5], db[5], out,  16,  16, 128, 128, 2);
}

// round 3
// speedup vs baseline: 1.6918x; 1.0802x over previous
#include <cuda_runtime.h>
#include <math.h>

// ---------------- scratch (allocation-free: __device__ globals) ----------------
__device__ float g_buf0[32u * 32 * 128 * 128];   // 64 MB ping
__device__ float g_buf1[32u * 32 * 128 * 128];   // 64 MB pong
__device__ float g_S[4096];
__device__ float g_Sh[4096];
__device__ float g_Sw[4096];

__device__ __forceinline__ float activate(float v, int act) {
    switch (act) {
        case 1: return v > 0.f ? v : 0.2f * v;                          // leaky 0.2
        case 2: return v > 0.f ? v : 0.f;                               // relu
        case 3: return fmaxf(v, 0.f) + log1pf(expf(-fabsf(v)));         // softplus
        default: return v;
    }
}

__device__ __forceinline__ void cp_async4(void* sdst, const void* gsrc, bool pred) {
    unsigned saddr = (unsigned)__cvta_generic_to_shared(sdst);
    int sz = pred ? 4 : 0;
    asm volatile("cp.async.ca.shared.global [%0], [%1], 4, %2;\n"
                 :: "r"(saddr), "l"(gsrc), "r"(sz));
}
__device__ __forceinline__ void cp_commit() { asm volatile("cp.async.commit_group;\n"); }
__device__ __forceinline__ void cp_wait0() { asm volatile("cp.async.wait_group 0;\n"); }

// =====================================================================
// stride-1 3x3 SAME conv. block: 32x16 out tile x OCB oc.
// thread: 4x2 px x 8 oc (64 acc). ICB=4 stages, cp.async double buffered.
// =====================================================================
template <int OCB>
__global__ void __launch_bounds__(64 * (OCB / 8), 512 / (64 * (OCB / 8))) conv_s1(
    const float* __restrict__ in, const float* __restrict__ wgt,
    const float* __restrict__ bias, float* __restrict__ out,
    int C, int OC, int H, int W, int act)
{
    constexpr int NT = 64 * (OCB / 8);
    constexpr int ICB = 4;
    constexpr int SROW = 34;           // 32 + 2, even -> float2-safe
    constexpr int SIN = 18 * SROW;     // 612

    const int tilesX = W >> 5;
    const int x0 = (blockIdx.x % tilesX) << 5;
    const int y0 = (blockIdx.x / tilesX) << 4;
    const int oc0 = blockIdx.y * OCB;
    const int b = blockIdx.z;

    __shared__ __align__(16) float s_in[2][ICB][SIN];
    __shared__ __align__(16) float s_w[2][ICB][OCB * 12];

    const int tid = threadIdx.x;
    const int g = tid >> 6;            // oc group of 8
    const int sp = tid & 63;
    const int ty = sp >> 3, tx = sp & 7;   // 8x8 thread grid
    // thread covers out px x: 4*tx..4*tx+3, y: 2*ty..2*ty+1 (within tile)

    float acc[8][2][4];
#pragma unroll
    for (int o = 0; o < 8; o++)
#pragma unroll
        for (int dy = 0; dy < 2; dy++)
#pragma unroll
            for (int dx = 0; dx < 4; dx++) acc[o][dy][dx] = 0.f;

    const float* inb = in + (size_t)b * C * H * W;
    const float* wb = wgt + (size_t)oc0 * C * 9;

    auto stage_copy = [&](int buf, int ic0, int cnt) {
        const float* ins = inb + (size_t)ic0 * H * W;
        for (int i = tid; i < cnt * SIN; i += NT) {
            int ch = i / SIN, r2 = i - ch * SIN;
            int r = r2 / SROW, c2 = r2 - r * SROW;
            int iy = y0 - 1 + r, ix = x0 - 1 + c2;
            bool p = (unsigned)iy < (unsigned)H && (unsigned)ix < (unsigned)W;
            cp_async4(&s_in[buf][ch][r2], ins + (size_t)ch * H * W + (size_t)iy * W + ix, p);
        }
        for (int i = tid; i < cnt * OCB * 9; i += NT) {
            int ch = i / (OCB * 9), r2 = i - ch * (OCB * 9);
            int o = r2 / 9, j2 = r2 - o * 9;
            cp_async4(&s_w[buf][ch][o * 12 + j2],
                      wb + ((size_t)o * C + ic0 + ch) * 9 + j2, true);
        }
    };

    const int sbase = (2 * ty) * SROW + 4 * tx;

    auto compute_ch = [&](int buf, int ch) {
        float rr[4][6];
        const float* si = &s_in[buf][ch][sbase];
#pragma unroll
        for (int r = 0; r < 4; r++) {
            const float2* p = (const float2*)(si + r * SROW);
            float2 a = p[0], b2 = p[1], c2 = p[2];
            rr[r][0] = a.x; rr[r][1] = a.y; rr[r][2] = b2.x;
            rr[r][3] = b2.y; rr[r][4] = c2.x; rr[r][5] = c2.y;
        }
#pragma unroll
        for (int o = 0; o < 8; o++) {
            const float4* wp = (const float4*)&s_w[buf][ch][(g * 8 + o) * 12];
            float4 wa = wp[0];
            float4 wc = wp[1];
            float w8 = ((const float*)wp)[8];
            // w0..w8 = wa.x wa.y wa.z wa.w wc.x wc.y wc.z wc.w w8
#pragma unroll
            for (int dy = 0; dy < 2; dy++)
#pragma unroll
                for (int dx = 0; dx < 4; dx++) {
                    float s = acc[o][dy][dx];
                    s += wa.x * rr[dy + 0][dx + 0];
                    s += wa.y * rr[dy + 0][dx + 1];
                    s += wa.z * rr[dy + 0][dx + 2];
                    s += wa.w * rr[dy + 1][dx + 0];
                    s += wc.x * rr[dy + 1][dx + 1];
                    s += wc.y * rr[dy + 1][dx + 2];
                    s += wc.z * rr[dy + 2][dx + 0];
                    s += wc.w * rr[dy + 2][dx + 1];
                    s += w8   * rr[dy + 2][dx + 2];
                    acc[o][dy][dx] = s;
                }
        }
    };

    const int nst = (C + ICB - 1) / ICB;
    stage_copy(0, 0, C < ICB ? C : ICB);
    cp_commit();
    for (int s = 0; s < nst; s++) {
        int buf = s & 1;
        cp_wait0();
        __syncthreads();
        int icn = (s + 1) * ICB;
        if (icn < C) {
            int cn = C - icn; if (cn > ICB) cn = ICB;
            stage_copy(buf ^ 1, icn, cn);
        }
        cp_commit();
        int cnt = C - s * ICB; if (cnt > ICB) cnt = ICB;
        if (cnt == ICB) {
#pragma unroll
            for (int j = 0; j < ICB; j++) compute_ch(buf, j);
        } else {
            for (int j = 0; j < cnt; j++) compute_ch(buf, j);
        }
    }

#pragma unroll
    for (int o = 0; o < 8; o++) {
        int oc = oc0 + g * 8 + o;
        float bv = bias[oc];
        float* ob = out + (((size_t)b * OC + oc) * H + y0 + 2 * ty) * (size_t)W + x0 + 4 * tx;
#pragma unroll
        for (int dy = 0; dy < 2; dy++) {
            float4 v;
            v.x = activate(acc[o][dy][0] + bv, act);
            v.y = activate(acc[o][dy][1] + bv, act);
            v.z = activate(acc[o][dy][2] + bv, act);
            v.w = activate(acc[o][dy][3] + bv, act);
            *(float4*)(ob + (size_t)dy * W) = v;
        }
    }
}

// =====================================================================
// stride-2 3x3 SAME conv (JAX: pad lo=0, hi=1). block: 16x16 out tile x OCB oc.
// thread: 2x2 out px x 8 oc. ICB=4 stages, cp.async double buffered.
// =====================================================================
template <int OCB>
__global__ void __launch_bounds__(64 * (OCB / 8), 512 / (64 * (OCB / 8))) conv_s2(
    const float* __restrict__ in, const float* __restrict__ wgt,
    const float* __restrict__ bias, float* __restrict__ out,
    int C, int OC, int Hout, int Wout, int act)
{
    constexpr int NT = 64 * (OCB / 8);
    constexpr int ICB = 4;
    constexpr int SIN = 33 * 33;  // 1089

    const int Hin = Hout * 2, Win = Wout * 2;
    const int tilesX = Wout >> 4;
    const int x0 = (blockIdx.x % tilesX) << 4;
    const int y0 = (blockIdx.x / tilesX) << 4;
    const int oc0 = blockIdx.y * OCB;
    const int b = blockIdx.z;

    __shared__ __align__(16) float s_in[2][ICB][SIN + 1];
    __shared__ __align__(16) float s_w[2][ICB][OCB * 12];

    const int tid = threadIdx.x;
    const int g = tid >> 6;
    const int sp = tid & 63;
    const int ty = sp >> 3, tx = sp & 7;

    float acc[8][4];
#pragma unroll
    for (int o = 0; o < 8; o++)
#pragma unroll
        for (int p = 0; p < 4; p++) acc[o][p] = 0.f;

    const float* inb = in + (size_t)b * C * Hin * Win;
    const float* wb = wgt + (size_t)oc0 * C * 9;

    auto stage_copy = [&](int buf, int ic0, int cnt) {
        const float* ins = inb + (size_t)ic0 * Hin * Win;
        for (int i = tid; i < cnt * SIN; i += NT) {
            int ch = i / SIN, r2 = i - ch * SIN;
            int r = r2 / 33, c2 = r2 - r * 33;
            int iy = 2 * y0 + r, ix = 2 * x0 + c2;
            bool p = iy < Hin && ix < Win;
            cp_async4(&s_in[buf][ch][r2], ins + (size_t)ch * Hin * Win + (size_t)iy * Win + ix, p);
        }
        for (int i = tid; i < cnt * OCB * 9; i += NT) {
            int ch = i / (OCB * 9), r2 = i - ch * (OCB * 9);
            int o = r2 / 9, j2 = r2 - o * 9;
            cp_async4(&s_w[buf][ch][o * 12 + j2],
                      wb + ((size_t)o * C + ic0 + ch) * 9 + j2, true);
        }
    };

    auto compute_ch = [&](int buf, int ch) {
        float rr[5][5];
#pragma unroll
        for (int r = 0; r < 5; r++)
#pragma unroll
            for (int c = 0; c < 5; c++)
                rr[r][c] = s_in[buf][ch][(4 * ty + r) * 33 + 4 * tx + c];
#pragma unroll
        for (int o = 0; o < 8; o++) {
            const float4* wp = (const float4*)&s_w[buf][ch][(g * 8 + o) * 12];
            float4 wa = wp[0];
            float4 wc = wp[1];
            float w8 = ((const float*)wp)[8];
#pragma unroll
            for (int dy = 0; dy < 2; dy++)
#pragma unroll
                for (int dx = 0; dx < 2; dx++) {
                    float s = acc[o][dy * 2 + dx];
                    s += wa.x * rr[2 * dy + 0][2 * dx + 0];
                    s += wa.y * rr[2 * dy + 0][2 * dx + 1];
                    s += wa.z * rr[2 * dy + 0][2 * dx + 2];
                    s += wa.w * rr[2 * dy + 1][2 * dx + 0];
                    s += wc.x * rr[2 * dy + 1][2 * dx + 1];
                    s += wc.y * rr[2 * dy + 1][2 * dx + 2];
                    s += wc.z * rr[2 * dy + 2][2 * dx + 0];
                    s += wc.w * rr[2 * dy + 2][2 * dx + 1];
                    s += w8   * rr[2 * dy + 2][2 * dx + 2];
                    acc[o][dy * 2 + dx] = s;
                }
        }
    };

    const int nst = (C + ICB - 1) / ICB;
    stage_copy(0, 0, C < ICB ? C : ICB);
    cp_commit();
    for (int s = 0; s < nst; s++) {
        int buf = s & 1;
        cp_wait0();
        __syncthreads();
        int icn = (s + 1) * ICB;
        if (icn < C) {
            int cn = C - icn; if (cn > ICB) cn = ICB;
            stage_copy(buf ^ 1, icn, cn);
        }
        cp_commit();
        int cnt = C - s * ICB; if (cnt > ICB) cnt = ICB;
        if (cnt == ICB) {
#pragma unroll
            for (int j = 0; j < ICB; j++) compute_ch(buf, j);
        } else {
            for (int j = 0; j < cnt; j++) compute_ch(buf, j);
        }
    }

#pragma unroll
    for (int o = 0; o < 8; o++) {
        int oc = oc0 + g * 8 + o;
        float bv = bias[oc];
        float* ob = out + (((size_t)b * OC + oc) * Hout + y0) * (size_t)Wout + x0;
#pragma unroll
        for (int dy = 0; dy < 2; dy++)
#pragma unroll
            for (int dx = 0; dx < 2; dx++)
                ob[(size_t)(2 * ty + dy) * Wout + 2 * tx + dx] =
                    activate(acc[o][dy * 2 + dx] + bv, act);
    }
}

// =====================================================================
// transposed conv 3x3 stride-2 SAME (JAX conv_transpose, pad_a=2):
// out[y] even: W[0]X[y/2-1] + W[2]X[y/2];  out[y] odd: W[1]X[(y-1)/2]
// block: 16x16 out tile x 16 oc. thread: 2x2 out px x 4 oc. relu epilogue.
// =====================================================================
__global__ void __launch_bounds__(256, 3) tconv_s2(
    const float* __restrict__ in, const float* __restrict__ wgt,
    const float* __restrict__ bias, float* __restrict__ out,
    int C, int OC, int Hout, int Wout)
{
    constexpr int NT = 256;
    constexpr int ICB = 4;
    constexpr int SIN = 9 * 9;  // 81

    const int Hin = Hout >> 1, Win = Wout >> 1;
    const int tilesX = Wout >> 4;
    const int x0 = (blockIdx.x % tilesX) << 4;
    const int y0 = (blockIdx.x / tilesX) << 4;
    const int oc0 = blockIdx.y * 16;
    const int b = blockIdx.z;
    const int Y0 = y0 >> 1, X0 = x0 >> 1;

    __shared__ __align__(16) float s_in[2][ICB][SIN + 3];
    __shared__ __align__(16) float s_w[2][ICB][16 * 12];

    const int tid = threadIdx.x;
    const int g = tid >> 6;            // 4 oc-groups of 4
    const int sp = tid & 63;
    const int ty = sp >> 3, tx = sp & 7;

    float acc[4][4];
#pragma unroll
    for (int o = 0; o < 4; o++)
#pragma unroll
        for (int p = 0; p < 4; p++) acc[o][p] = 0.f;

    const float* inb = in + (size_t)b * C * Hin * Win;
    const float* wb = wgt + (size_t)oc0 * C * 9;

    auto stage_copy = [&](int buf, int ic0, int cnt) {
        const float* ins = inb + (size_t)ic0 * Hin * Win;
        for (int i = tid; i < cnt * SIN; i += NT) {
            int ch = i / SIN, r2 = i - ch * SIN;
            int r = r2 / 9, c2 = r2 - r * 9;
            int iy = Y0 - 1 + r, ix = X0 - 1 + c2;
            bool p = (unsigned)iy < (unsigned)Hin && (unsigned)ix < (unsigned)Win;
            cp_async4(&s_in[buf][ch][r2], ins + (size_t)ch * Hin * Win + (size_t)iy * Win + ix, p);
        }
        for (int i = tid; i < cnt * 16 * 9; i += NT) {
            int ch = i / (16 * 9), r2 = i - ch * (16 * 9);
            int o = r2 / 9, j2 = r2 - o * 9;
            cp_async4(&s_w[buf][ch][o * 12 + j2],
                      wb + ((size_t)o * C + ic0 + ch) * 9 + j2, true);
        }
    };

    auto compute_ch = [&](int buf, int ch) {
        const float* si = s_in[buf][ch];
        float r00 = si[ty * 9 + tx];
        float r01 = si[ty * 9 + tx + 1];
        float r10 = si[(ty + 1) * 9 + tx];
        float r11 = si[(ty + 1) * 9 + tx + 1];
#pragma unroll
        for (int o = 0; o < 4; o++) {
            const float4* wp = (const float4*)&s_w[buf][ch][(g * 4 + o) * 12];
            float4 wa = wp[0];
            float4 wc = wp[1];
            float w8 = ((const float*)wp)[8];
            acc[o][0] += wa.x * r00 + wa.z * r01 + wc.z * r10 + w8 * r11;
            acc[o][1] += wa.y * r01 + wc.w * r11;
            acc[o][2] += wa.w * r10 + wc.y * r11;
            acc[o][3] += wc.x * r11;
        }
    };

    const int nst = (C + ICB - 1) / ICB;
    stage_copy(0, 0, C < ICB ? C : ICB);
    cp_commit();
    for (int s = 0; s < nst; s++) {
        int buf = s & 1;
        cp_wait0();
        __syncthreads();
        int icn = (s + 1) * ICB;
        if (icn < C) {
            int cn = C - icn; if (cn > ICB) cn = ICB;
            stage_copy(buf ^ 1, icn, cn);
        }
        cp_commit();
        int cnt = C - s * ICB; if (cnt > ICB) cnt = ICB;
        if (cnt == ICB) {
#pragma unroll
            for (int j = 0; j < ICB; j++) compute_ch(buf, j);
        } else {
            for (int j = 0; j < cnt; j++) compute_ch(buf, j);
        }
    }

#pragma unroll
    for (int o = 0; o < 4; o++) {
        int oc = oc0 + g * 4 + o;
        float bv = bias[oc];
        float* ob = out + (((size_t)b * OC + oc) * Hout + y0) * (size_t)Wout + x0;
#pragma unroll
        for (int dy = 0; dy < 2; dy++)
#pragma unroll
            for (int dx = 0; dx < 2; dx++) {
                float v = acc[o][dy * 2 + dx] + bv;
                ob[(size_t)(2 * ty + dy) * Wout + 2 * tx + dx] = v > 0.f ? v : 0.f;
            }
    }
}

// ---------------- keypoint bottleneck ----------------
__global__ void bn_stats(const float* __restrict__ R, float* __restrict__ S,
                         float* __restrict__ Sh, float* __restrict__ Sw)
{
    int bk = blockIdx.x;
    int t = threadIdx.x;
    float v = R[(size_t)bk * 256 + t];
    float a = v;
    float bsum = v * (float)(t >> 4);
    float c = v * (float)(t & 15);
#pragma unroll
    for (int off = 16; off > 0; off >>= 1) {
        a += __shfl_down_sync(0xffffffffu, a, off);
        bsum += __shfl_down_sync(0xffffffffu, bsum, off);
        c += __shfl_down_sync(0xffffffffu, c, off);
    }
    __shared__ float sa[8], sb[8], sc[8];
    int wid = t >> 5;
    if ((t & 31) == 0) { sa[wid] = a; sb[wid] = bsum; sc[wid] = c; }
    __syncthreads();
    if (t == 0) {
        float ta = 0.f, tb = 0.f, tc = 0.f;
        for (int i = 0; i < 8; i++) { ta += sa[i]; tb += sb[i]; tc += sc[i]; }
        S[bk] = ta; Sh[bk] = tb; Sw[bk] = tc;
    }
}

__global__ void bn_maps(const float* __restrict__ S, const float* __restrict__ Sh,
                        const float* __restrict__ Sw, float* __restrict__ maps)
{
    int bk = blockIdx.x;
    int b = bk >> 7;
    float s = S[bk];
    float denom = S[(b << 7) | 127];
    float mu = s * (1.f / 256.f);
    float inv = 1.f / denom;
    float c0 = Sh[bk] * inv;
    float c1 = Sw[bk] * inv;
    int t = threadIdx.x;
    float h = (float)(t >> 4), w = (float)(t & 15);
    float dh = h - c0, dw = w - c1;
    maps[(size_t)bk * 256 + t] = mu * expf(-0.5f * (dh * dh + dw * dw));
}

// ---------------- launch ----------------
extern "C" void kernel_launch(void* const* d_in, const int* in_sizes, int n_in,
                              void* d_out, int out_size)
{
    (void)in_sizes; (void)n_in; (void)out_size;
    const float* x = (const float*)d_in[0];
    const float* ew[7]; const float* eb[7];
    for (int j = 0; j < 7; j++) {
        ew[j] = (const float*)d_in[1 + 2 * j];
        eb[j] = (const float*)d_in[2 + 2 * j];
    }
    const float* dw[6]; const float* db[6];
    for (int j = 0; j < 6; j++) {
        dw[j] = (const float*)d_in[15 + 2 * j];
        db[j] = (const float*)d_in[16 + 2 * j];
    }
    float* out = (float*)d_out;

    float *buf0, *buf1, *S, *Sh, *Sw;
    cudaGetSymbolAddress((void**)&buf0, g_buf0);
    cudaGetSymbolAddress((void**)&buf1, g_buf1);
    cudaGetSymbolAddress((void**)&S, g_S);
    cudaGetSymbolAddress((void**)&Sh, g_Sh);
    cudaGetSymbolAddress((void**)&Sw, g_Sw);

    const int B = 32;
    // ---- encoder ---- (conv_s1 tiles are 32x16)
    conv_s1<32><<<dim3(32, 1, B), 256>>>(x,    ew[0], eb[0], buf0, 3,   32, 128, 128, 0);
    conv_s1<32><<<dim3(32, 1, B), 256>>>(buf0, ew[1], eb[1], buf1, 32,  32, 128, 128, 0);
    conv_s2<32><<<dim3(16, 2, B), 256>>>(buf1, ew[2], eb[2], buf0, 32,  64, 64, 64, 1);
    conv_s1<32><<<dim3(8, 2, B),  256>>>(buf0, ew[3], eb[3], buf1, 64,  64, 64, 64, 1);
    conv_s2<32><<<dim3(4, 4, B),  256>>>(buf1, ew[4], eb[4], buf0, 64, 128, 32, 32, 1);
    conv_s1<32><<<dim3(2, 4, B),  256>>>(buf0, ew[5], eb[5], buf1, 128, 128, 32, 32, 1);
    conv_s2<8> <<<dim3(1, 16, B), 64>>> (buf1, ew[6], eb[6], buf0, 128, 128, 16, 16, 3);
    // ---- keypoint bottleneck ----
    bn_stats<<<4096, 256>>>(buf0, S, Sh, Sw);
    bn_maps <<<4096, 256>>>(S, Sh, Sw, buf1);
    // ---- decoder ----
    tconv_s2   <<<dim3(4, 4, B),  256>>>(buf1, dw[0], db[0], buf0, 128, 64, 32, 32);
    conv_s1<32><<<dim3(2, 2, B),  256>>>(buf0, dw[1], db[1], buf1, 64,  64, 32, 32, 2);
    tconv_s2   <<<dim3(16, 2, B), 256>>>(buf1, dw[2], db[2], buf0, 64,  32, 64, 64);
    conv_s1<32><<<dim3(8, 1, B),  256>>>(buf0, dw[3], db[3], buf1, 32,  32, 64, 64, 2);
    tconv_s2   <<<dim3(64, 1, B), 256>>>(buf1, dw[4], db[4], buf0, 32,  16, 128, 128);
    conv_s1<16><<<dim3(32, 1, B), 128>>>(buf0, dw[5], db[5], out,  16,  16, 128, 128, 2);
}

// round 4
// speedup vs baseline: 1.7842x; 1.0546x over previous
#include <cuda_runtime.h>
#include <cuda_bf16.h>
#include <math.h>

// ---------------- scratch (allocation-free: __device__ globals) ----------------
__device__ unsigned g_buf0[32u * 32 * 128 * 128];   // 64 MB ping (packed NHWC)
__device__ unsigned g_buf1[32u * 32 * 128 * 128];   // 64 MB pong
__device__ uint4    g_wprep[60480];                 // pre-split mma weights
__device__ float g_S[4096];
__device__ float g_Sh[4096];
__device__ float g_Sw[4096];

__device__ __forceinline__ float activate(float v, int act) {
    switch (act) {
        case 1: return v > 0.f ? v : 0.2f * v;                          // leaky 0.2
        case 2: return v > 0.f ? v : 0.f;                               // relu
        case 3: return fmaxf(v, 0.f) + log1pf(expf(-fabsf(v)));         // softplus
        default: return v;
    }
}

// packed hi/lo bf16 activation format: bits[31:16]=bf16(x), bits[15:0]=bf16(x-hi)
__device__ __forceinline__ unsigned pack_hl(float x) {
    unsigned h = (unsigned)__bfloat16_as_ushort(__float2bfloat16(x)) << 16;
    float hf = __uint_as_float(h);
    unsigned l = (unsigned)__bfloat16_as_ushort(__float2bfloat16(x - hf));
    return h | l;
}
__device__ __forceinline__ float unpack_hl(unsigned p) {
    return __uint_as_float(p & 0xffff0000u) + __uint_as_float(p << 16);
}
__device__ __forceinline__ unsigned pack2_bf16(float e_lo, float e_hi) {
    return ((unsigned)__bfloat16_as_ushort(__float2bfloat16(e_hi)) << 16)
         | (unsigned)__bfloat16_as_ushort(__float2bfloat16(e_lo));
}

__device__ __forceinline__ void cp_async4(void* sdst, const void* gsrc, bool pred) {
    unsigned saddr = (unsigned)__cvta_generic_to_shared(sdst);
    int sz = pred ? 4 : 0;
    asm volatile("cp.async.ca.shared.global [%0], [%1], 4, %2;\n"
                 :: "r"(saddr), "l"(gsrc), "r"(sz));
}
__device__ __forceinline__ void cp_async16(void* sdst, const void* gsrc, bool pred) {
    unsigned saddr = (unsigned)__cvta_generic_to_shared(sdst);
    int sz = pred ? 16 : 0;
    asm volatile("cp.async.cg.shared.global [%0], [%1], 16, %2;\n"
                 :: "r"(saddr), "l"(gsrc), "r"(sz));
}
__device__ __forceinline__ void cp_commit() { asm volatile("cp.async.commit_group;\n"); }
__device__ __forceinline__ void cp_wait0() { asm volatile("cp.async.wait_group 0;\n"); }

__device__ __forceinline__ void mma16816(float* d, const unsigned* a, unsigned b0, unsigned b1) {
    asm volatile("mma.sync.aligned.m16n8k16.row.col.f32.bf16.bf16.f32 "
                 "{%0,%1,%2,%3},{%4,%5,%6,%7},{%8,%9},{%0,%1,%2,%3};"
                 : "+f"(d[0]), "+f"(d[1]), "+f"(d[2]), "+f"(d[3])
                 : "r"(a[0]), "r"(a[1]), "r"(a[2]), "r"(a[3]), "r"(b0), "r"(b1));
}

// =====================================================================
// weight prep: OIHW fp32 -> fragment-ready hi/lo bf16x2, layout
// [(kc*9 + t)*(OC/8) + og]*32 + lane, uint4 = (b0h, b1h, b0l, b1l)
// =====================================================================
__global__ void prep_w(const float* __restrict__ w, uint4* __restrict__ dst, int C, int OC) {
    int idx = blockIdx.x * 256 + threadIdx.x;
    int OCg = OC >> 3;
    int total = (C >> 4) * 9 * OCg * 32;
    if (idx >= total) return;
    int l = idx & 31;
    int q = idx >> 5;
    int og = q % OCg; q /= OCg;
    int t = q % 9;
    int kc = q / 9;
    int tg = l & 3, gg = l >> 2;
    int n = og * 8 + gg;                           // oc
    float h[4], lo[4];
#pragma unroll
    for (int kk = 0; kk < 4; kk++) {
        int k = (kk < 2) ? (2 * tg + kk) : (2 * tg + 8 + (kk - 2));
        int ic = (kc << 4) + k;
        float e = w[((size_t)n * C + ic) * 9 + t];
        unsigned hb = (unsigned)__bfloat16_as_ushort(__float2bfloat16(e)) << 16;
        h[kk] = __uint_as_float(hb);
        lo[kk] = e - h[kk];
    }
    uint4 r;
    r.x = pack2_bf16(h[0], h[1]);
    r.y = pack2_bf16(h[2], h[3]);
    r.z = pack2_bf16(lo[0], lo[1]);
    r.w = pack2_bf16(lo[2], lo[3]);
    dst[idx] = r;
}

// =====================================================================
// tensor-core stride-1 3x3 SAME conv (bf16x3 split, fp32 accum).
// block: 16x16 px tile x 32 oc. 8 warps; warp owns 2 tile rows.
// input: packed NHWC. output: packed NHWC (fp32out=0) or fp32 NCHW (=1).
// =====================================================================
#define MMA_SIN (324 * 20)
#define MMA_SW  (9 * 4 * 32)
#define MMA_SMEM (2 * MMA_SIN * 4 + 2 * MMA_SW * 16)

__global__ void __launch_bounds__(256, 2) conv_mma_s1(
    const unsigned* __restrict__ in, const uint4* __restrict__ wp,
    const float* __restrict__ bias, void* __restrict__ outp,
    int C, int OC, int H, int W, int act, int fp32out)
{
    const int KC = C >> 4;
    const int tilesX = W >> 4;
    const int x0 = (blockIdx.x % tilesX) << 4;
    const int y0 = (blockIdx.x / tilesX) << 4;
    const int oc0 = blockIdx.y << 5;
    const int b = blockIdx.z;
    const int OCg = OC >> 3;
    int nf = OCg - (oc0 >> 3); if (nf > 4) nf = 4;

    extern __shared__ __align__(16) unsigned char dsm[];
    unsigned* s_in = (unsigned*)dsm;                       // [2][324*20]
    uint4* s_w = (uint4*)(dsm + 2 * MMA_SIN * 4);          // [2][9*4*32]

    const unsigned* inb = in + (size_t)b * H * W * C;
    const int tid = threadIdx.x, lane = tid & 31, wid = tid >> 5;
    const int g = lane >> 2, tg = lane & 3;

    float d[2][4][4];
#pragma unroll
    for (int i = 0; i < 2; i++)
#pragma unroll
        for (int j = 0; j < 4; j++)
#pragma unroll
            for (int r = 0; r < 4; r++) d[i][j][r] = 0.f;

    auto stage = [&](int buf, int kc) {
        unsigned* si = s_in + buf * MMA_SIN;
        for (int i = tid; i < 324 * 4; i += 256) {
            int sp = i >> 2, q = i & 3;
            int r = sp / 18, c = sp - r * 18;
            int iy = y0 - 1 + r, ix = x0 - 1 + c;
            bool p = (unsigned)iy < (unsigned)H && (unsigned)ix < (unsigned)W;
            cp_async16(si + sp * 20 + q * 4,
                       inb + ((size_t)iy * W + ix) * C + (kc << 4) + q * 4, p);
        }
        uint4* sw = s_w + buf * MMA_SW;
        const uint4* wsrc = wp + (size_t)kc * 9 * OCg * 32;
        int tot = 9 * nf * 32;
        for (int i = tid; i < tot; i += 256) {
            int l = i & 31;
            int q = i >> 5;
            int ogl = q % nf;
            int t = q / nf;
            cp_async16(sw + (t * 4 + ogl) * 32 + l,
                       wsrc + ((size_t)t * OCg + (oc0 >> 3) + ogl) * 32 + l, true);
        }
    };

    auto compute = [&](int buf) {
        unsigned* si = s_in + buf * MMA_SIN;
        uint4* sw = s_w + buf * MMA_SW;
#pragma unroll
        for (int t = 0; t < 9; t++) {
            const int dy = t / 3, dx = t - 3 * (t / 3);
            unsigned ah[2][4], al[2][4];
#pragma unroll
            for (int i = 0; i < 2; i++) {
                int sp0 = (2 * wid + i + dy) * 18 + g + dx;
                int sp1 = sp0 + 8;
                uint2 u00 = *(const uint2*)(si + sp0 * 20 + 2 * tg);
                uint2 u10 = *(const uint2*)(si + sp1 * 20 + 2 * tg);
                uint2 u01 = *(const uint2*)(si + sp0 * 20 + 2 * tg + 8);
                uint2 u11 = *(const uint2*)(si + sp1 * 20 + 2 * tg + 8);
                ah[i][0] = __byte_perm(u00.x, u00.y, 0x7632);
                al[i][0] = __byte_perm(u00.x, u00.y, 0x5410);
                ah[i][1] = __byte_perm(u10.x, u10.y, 0x7632);
                al[i][1] = __byte_perm(u10.x, u10.y, 0x5410);
                ah[i][2] = __byte_perm(u01.x, u01.y, 0x7632);
                al[i][2] = __byte_perm(u01.x, u01.y, 0x5410);
                ah[i][3] = __byte_perm(u11.x, u11.y, 0x7632);
                al[i][3] = __byte_perm(u11.x, u11.y, 0x5410);
            }
            for (int j = 0; j < nf; j++) {
                uint4 bw = sw[(t * 4 + j) * 32 + lane];
#pragma unroll
                for (int i = 0; i < 2; i++) {
                    mma16816(d[i][j], ah[i], bw.x, bw.y);   // hi*hi
                    mma16816(d[i][j], al[i], bw.x, bw.y);   // lo*hi
                    mma16816(d[i][j], ah[i], bw.z, bw.w);   // hi*lo
                }
            }
        }
    };

    stage(0, 0);
    cp_commit();
    for (int kc = 0; kc < KC; kc++) {
        int buf = kc & 1;
        cp_wait0();
        __syncthreads();
        if (kc + 1 < KC) stage(buf ^ 1, kc + 1);
        cp_commit();
        compute(buf);
    }

    // epilogue: D[i][j]: rows(x) = g/g+8, cols(oc) = 8j+2tg(+1); y = y0+2*wid+i
    if (!fp32out) {
        unsigned* ob = (unsigned*)outp + (size_t)b * H * W * OC;
#pragma unroll
        for (int i = 0; i < 2; i++) {
            int y = y0 + 2 * wid + i;
            for (int j = 0; j < nf; j++) {
                int oc = oc0 + 8 * j + 2 * tg;
                float b0 = bias[oc], b1 = bias[oc + 1];
                uint2 v0, v1;
                v0.x = pack_hl(activate(d[i][j][0] + b0, act));
                v0.y = pack_hl(activate(d[i][j][1] + b1, act));
                v1.x = pack_hl(activate(d[i][j][2] + b0, act));
                v1.y = pack_hl(activate(d[i][j][3] + b1, act));
                *(uint2*)(ob + ((size_t)y * W + x0 + g) * OC + oc) = v0;
                *(uint2*)(ob + ((size_t)y * W + x0 + g + 8) * OC + oc) = v1;
            }
        }
    } else {
        float* of = (float*)outp;
#pragma unroll
        for (int i = 0; i < 2; i++) {
            int y = y0 + 2 * wid + i;
            for (int j = 0; j < nf; j++) {
                int oc = oc0 + 8 * j + 2 * tg;
                float b0 = bias[oc], b1 = bias[oc + 1];
                size_t base0 = (((size_t)b * OC + oc) * H + y) * W + x0;
                size_t base1 = base0 + (size_t)H * W;
                of[base0 + g]     = activate(d[i][j][0] + b0, act);
                of[base1 + g]     = activate(d[i][j][1] + b1, act);
                of[base0 + g + 8] = activate(d[i][j][2] + b0, act);
                of[base1 + g + 8] = activate(d[i][j][3] + b1, act);
            }
        }
    }
}

// =====================================================================
// e0 scalar conv: fp32 NCHW input (C=3), packed NHWC output.
// block: 32x16 out tile x 32 oc. thread: 4x2 px x 8 oc.
// =====================================================================
__global__ void __launch_bounds__(256, 2) conv_e0(
    const float* __restrict__ in, const float* __restrict__ wgt,
    const float* __restrict__ bias, unsigned* __restrict__ out,
    int C, int OC, int H, int W, int act)
{
    constexpr int NT = 256;
    constexpr int ICB = 4;
    constexpr int SROW = 34;
    constexpr int SIN = 18 * SROW;

    const int tilesX = W >> 5;
    const int x0 = (blockIdx.x % tilesX) << 5;
    const int y0 = (blockIdx.x / tilesX) << 4;
    const int oc0 = blockIdx.y * 32;
    const int b = blockIdx.z;

    __shared__ __align__(16) float s_in[2][ICB][SIN];
    __shared__ __align__(16) float s_w[2][ICB][32 * 12];

    const int tid = threadIdx.x;
    const int g = tid >> 6;
    const int sp = tid & 63;
    const int ty = sp >> 3, tx = sp & 7;

    float acc[8][2][4];
#pragma unroll
    for (int o = 0; o < 8; o++)
#pragma unroll
        for (int dy = 0; dy < 2; dy++)
#pragma unroll
            for (int dx = 0; dx < 4; dx++) acc[o][dy][dx] = 0.f;

    const float* inb = in + (size_t)b * C * H * W;
    const float* wb = wgt + (size_t)oc0 * C * 9;

    auto stage_copy = [&](int buf, int ic0, int cnt) {
        const float* ins = inb + (size_t)ic0 * H * W;
        for (int i = tid; i < cnt * SIN; i += NT) {
            int ch = i / SIN, r2 = i - ch * SIN;
            int r = r2 / SROW, c2 = r2 - r * SROW;
            int iy = y0 - 1 + r, ix = x0 - 1 + c2;
            bool p = (unsigned)iy < (unsigned)H && (unsigned)ix < (unsigned)W;
            cp_async4(&s_in[buf][ch][r2], ins + (size_t)ch * H * W + (size_t)iy * W + ix, p);
        }
        for (int i = tid; i < cnt * 32 * 9; i += NT) {
            int ch = i / (32 * 9), r2 = i - ch * (32 * 9);
            int o = r2 / 9, j2 = r2 - o * 9;
            cp_async4(&s_w[buf][ch][o * 12 + j2],
                      wb + ((size_t)o * C + ic0 + ch) * 9 + j2, true);
        }
    };

    const int sbase = (2 * ty) * SROW + 4 * tx;

    auto compute_ch = [&](int buf, int ch) {
        float rr[4][6];
        const float* si = &s_in[buf][ch][sbase];
#pragma unroll
        for (int r = 0; r < 4; r++) {
            const float2* p = (const float2*)(si + r * SROW);
            float2 a = p[0], b2 = p[1], c2 = p[2];
            rr[r][0] = a.x; rr[r][1] = a.y; rr[r][2] = b2.x;
            rr[r][3] = b2.y; rr[r][4] = c2.x; rr[r][5] = c2.y;
        }
#pragma unroll
        for (int o = 0; o < 8; o++) {
            const float4* wp = (const float4*)&s_w[buf][ch][(g * 8 + o) * 12];
            float4 wa = wp[0];
            float4 wc = wp[1];
            float w8 = ((const float*)wp)[8];
#pragma unroll
            for (int dy = 0; dy < 2; dy++)
#pragma unroll
                for (int dx = 0; dx < 4; dx++) {
                    float s = acc[o][dy][dx];
                    s += wa.x * rr[dy + 0][dx + 0];
                    s += wa.y * rr[dy + 0][dx + 1];
                    s += wa.z * rr[dy + 0][dx + 2];
                    s += wa.w * rr[dy + 1][dx + 0];
                    s += wc.x * rr[dy + 1][dx + 1];
                    s += wc.y * rr[dy + 1][dx + 2];
                    s += wc.z * rr[dy + 2][dx + 0];
                    s += wc.w * rr[dy + 2][dx + 1];
                    s += w8   * rr[dy + 2][dx + 2];
                    acc[o][dy][dx] = s;
                }
        }
    };

    const int nst = (C + ICB - 1) / ICB;
    stage_copy(0, 0, C < ICB ? C : ICB);
    cp_commit();
    for (int s = 0; s < nst; s++) {
        int buf = s & 1;
        cp_wait0();
        __syncthreads();
        int icn = (s + 1) * ICB;
        if (icn < C) {
            int cn = C - icn; if (cn > ICB) cn = ICB;
            stage_copy(buf ^ 1, icn, cn);
        }
        cp_commit();
        int cnt = C - s * ICB; if (cnt > ICB) cnt = ICB;
        for (int j = 0; j < cnt; j++) compute_ch(buf, j);
    }

    float bv[8];
#pragma unroll
    for (int o = 0; o < 8; o++) bv[o] = bias[oc0 + g * 8 + o];
    unsigned* ob = out + (size_t)b * H * W * OC;
#pragma unroll
    for (int dy = 0; dy < 2; dy++)
#pragma unroll
        for (int dx = 0; dx < 4; dx++) {
            int y = y0 + 2 * ty + dy, x = x0 + 4 * tx + dx;
            uint4 p0, p1;
            p0.x = pack_hl(activate(acc[0][dy][dx] + bv[0], act));
            p0.y = pack_hl(activate(acc[1][dy][dx] + bv[1], act));
            p0.z = pack_hl(activate(acc[2][dy][dx] + bv[2], act));
            p0.w = pack_hl(activate(acc[3][dy][dx] + bv[3], act));
            p1.x = pack_hl(activate(acc[4][dy][dx] + bv[4], act));
            p1.y = pack_hl(activate(acc[5][dy][dx] + bv[5], act));
            p1.z = pack_hl(activate(acc[6][dy][dx] + bv[6], act));
            p1.w = pack_hl(activate(acc[7][dy][dx] + bv[7], act));
            uint4* dst = (uint4*)(ob + ((size_t)y * W + x) * OC + oc0 + g * 8);
            dst[0] = p0;
            dst[1] = p1;
        }
}

// =====================================================================
// stride-2 3x3 SAME conv (pad lo=0, hi=1). packed NHWC in/out.
// =====================================================================
template <int OCB>
__global__ void __launch_bounds__(64 * (OCB / 8), 512 / (64 * (OCB / 8))) conv_s2(
    const unsigned* __restrict__ in, const float* __restrict__ wgt,
    const float* __restrict__ bias, unsigned* __restrict__ out,
    int C, int OC, int Hout, int Wout, int act)
{
    constexpr int NT = 64 * (OCB / 8);
    constexpr int ICB = 4;
    constexpr int SIN = 33 * 33;

    const int Hin = Hout * 2, Win = Wout * 2;
    const int tilesX = Wout >> 4;
    const int x0 = (blockIdx.x % tilesX) << 4;
    const int y0 = (blockIdx.x / tilesX) << 4;
    const int oc0 = blockIdx.y * OCB;
    const int b = blockIdx.z;

    __shared__ __align__(16) unsigned s_in[2][ICB][SIN + 1];
    __shared__ __align__(16) float s_w[2][ICB][OCB * 12];

    const int tid = threadIdx.x;
    const int g = tid >> 6;
    const int sp = tid & 63;
    const int ty = sp >> 3, tx = sp & 7;

    float acc[8][4];
#pragma unroll
    for (int o = 0; o < 8; o++)
#pragma unroll
        for (int p = 0; p < 4; p++) acc[o][p] = 0.f;

    const unsigned* inb = in + (size_t)b * Hin * Win * C;
    const float* wb = wgt + (size_t)oc0 * C * 9;

    auto stage_copy = [&](int buf, int ic0, int cnt) {
        for (int i = tid; i < cnt * SIN; i += NT) {
            int ch = i / SIN, r2 = i - ch * SIN;
            int r = r2 / 33, c2 = r2 - r * 33;
            int iy = 2 * y0 + r, ix = 2 * x0 + c2;
            bool p = iy < Hin && ix < Win;
            cp_async4(&s_in[buf][ch][r2],
                      inb + ((size_t)iy * Win + ix) * C + ic0 + ch, p);
        }
        for (int i = tid; i < cnt * OCB * 9; i += NT) {
            int ch = i / (OCB * 9), r2 = i - ch * (OCB * 9);
            int o = r2 / 9, j2 = r2 - o * 9;
            cp_async4(&s_w[buf][ch][o * 12 + j2],
                      wb + ((size_t)o * C + ic0 + ch) * 9 + j2, true);
        }
    };

    auto compute_ch = [&](int buf, int ch) {
        float rr[5][5];
#pragma unroll
        for (int r = 0; r < 5; r++)
#pragma unroll
            for (int c = 0; c < 5; c++)
                rr[r][c] = unpack_hl(s_in[buf][ch][(4 * ty + r) * 33 + 4 * tx + c]);
#pragma unroll
        for (int o = 0; o < 8; o++) {
            const float4* wp = (const float4*)&s_w[buf][ch][(g * 8 + o) * 12];
            float4 wa = wp[0];
            float4 wc = wp[1];
            float w8 = ((const float*)wp)[8];
#pragma unroll
            for (int dy = 0; dy < 2; dy++)
#pragma unroll
                for (int dx = 0; dx < 2; dx++) {
                    float s = acc[o][dy * 2 + dx];
                    s += wa.x * rr[2 * dy + 0][2 * dx + 0];
                    s += wa.y * rr[2 * dy + 0][2 * dx + 1];
                    s += wa.z * rr[2 * dy + 0][2 * dx + 2];
                    s += wa.w * rr[2 * dy + 1][2 * dx + 0];
                    s += wc.x * rr[2 * dy + 1][2 * dx + 1];
                    s += wc.y * rr[2 * dy + 1][2 * dx + 2];
                    s += wc.z * rr[2 * dy + 2][2 * dx + 0];
                    s += wc.w * rr[2 * dy + 2][2 * dx + 1];
                    s += w8   * rr[2 * dy + 2][2 * dx + 2];
                    acc[o][dy * 2 + dx] = s;
                }
        }
    };

    const int nst = (C + ICB - 1) / ICB;
    stage_copy(0, 0, C < ICB ? C : ICB);
    cp_commit();
    for (int s = 0; s < nst; s++) {
        int buf = s & 1;
        cp_wait0();
        __syncthreads();
        int icn = (s + 1) * ICB;
        if (icn < C) {
            int cn = C - icn; if (cn > ICB) cn = ICB;
            stage_copy(buf ^ 1, icn, cn);
        }
        cp_commit();
        int cnt = C - s * ICB; if (cnt > ICB) cnt = ICB;
        if (cnt == ICB) {
#pragma unroll
            for (int j = 0; j < ICB; j++) compute_ch(buf, j);
        } else {
            for (int j = 0; j < cnt; j++) compute_ch(buf, j);
        }
    }

    float bv[8];
#pragma unroll
    for (int o = 0; o < 8; o++) bv[o] = bias[oc0 + g * 8 + o];
    unsigned* ob = out + (size_t)b * Hout * Wout * OC;
#pragma unroll
    for (int dy = 0; dy < 2; dy++)
#pragma unroll
        for (int dx = 0; dx < 2; dx++) {
            int y = y0 + 2 * ty + dy, x = x0 + 2 * tx + dx;
            uint4 p0, p1;
            p0.x = pack_hl(activate(acc[0][dy * 2 + dx] + bv[0], act));
            p0.y = pack_hl(activate(acc[1][dy * 2 + dx] + bv[1], act));
            p0.z = pack_hl(activate(acc[2][dy * 2 + dx] + bv[2], act));
            p0.w = pack_hl(activate(acc[3][dy * 2 + dx] + bv[3], act));
            p1.x = pack_hl(activate(acc[4][dy * 2 + dx] + bv[4], act));
            p1.y = pack_hl(activate(acc[5][dy * 2 + dx] + bv[5], act));
            p1.z = pack_hl(activate(acc[6][dy * 2 + dx] + bv[6], act));
            p1.w = pack_hl(activate(acc[7][dy * 2 + dx] + bv[7], act));
            uint4* dst = (uint4*)(ob + ((size_t)y * Wout + x) * OC + oc0 + g * 8);
            dst[0] = p0;
            dst[1] = p1;
        }
}

// =====================================================================
// transposed conv 3x3 stride-2 SAME (pad_a=2). packed NHWC in/out. relu.
// =====================================================================
__global__ void __launch_bounds__(256, 3) tconv_s2(
    const unsigned* __restrict__ in, const float* __restrict__ wgt,
    const float* __restrict__ bias, unsigned* __restrict__ out,
    int C, int OC, int Hout, int Wout)
{
    constexpr int NT = 256;
    constexpr int ICB = 4;
    constexpr int SIN = 9 * 9;

    const int Hin = Hout >> 1, Win = Wout >> 1;
    const int tilesX = Wout >> 4;
    const int x0 = (blockIdx.x % tilesX) << 4;
    const int y0 = (blockIdx.x / tilesX) << 4;
    const int oc0 = blockIdx.y * 16;
    const int b = blockIdx.z;
    const int Y0 = y0 >> 1, X0 = x0 >> 1;

    __shared__ __align__(16) unsigned s_in[2][ICB][SIN + 3];
    __shared__ __align__(16) float s_w[2][ICB][16 * 12];

    const int tid = threadIdx.x;
    const int g = tid >> 6;
    const int sp = tid & 63;
    const int ty = sp >> 3, tx = sp & 7;

    float acc[4][4];
#pragma unroll
    for (int o = 0; o < 4; o++)
#pragma unroll
        for (int p = 0; p < 4; p++) acc[o][p] = 0.f;

    const unsigned* inb = in + (size_t)b * Hin * Win * C;
    const float* wb = wgt + (size_t)oc0 * C * 9;

    auto stage_copy = [&](int buf, int ic0, int cnt) {
        for (int i = tid; i < cnt * SIN; i += NT) {
            int ch = i / SIN, r2 = i - ch * SIN;
            int r = r2 / 9, c2 = r2 - r * 9;
            int iy = Y0 - 1 + r, ix = X0 - 1 + c2;
            bool p = (unsigned)iy < (unsigned)Hin && (unsigned)ix < (unsigned)Win;
            cp_async4(&s_in[buf][ch][r2],
                      inb + ((size_t)iy * Win + ix) * C + ic0 + ch, p);
        }
        for (int i = tid; i < cnt * 16 * 9; i += NT) {
            int ch = i / (16 * 9), r2 = i - ch * (16 * 9);
            int o = r2 / 9, j2 = r2 - o * 9;
            cp_async4(&s_w[buf][ch][o * 12 + j2],
                      wb + ((size_t)o * C + ic0 + ch) * 9 + j2, true);
        }
    };

    auto compute_ch = [&](int buf, int ch) {
        const unsigned* si = s_in[buf][ch];
        float r00 = unpack_hl(si[ty * 9 + tx]);
        float r01 = unpack_hl(si[ty * 9 + tx + 1]);
        float r10 = unpack_hl(si[(ty + 1) * 9 + tx]);
        float r11 = unpack_hl(si[(ty + 1) * 9 + tx + 1]);
#pragma unroll
        for (int o = 0; o < 4; o++) {
            const float4* wp = (const float4*)&s_w[buf][ch][(g * 4 + o) * 12];
            float4 wa = wp[0];
            float4 wc = wp[1];
            float w8 = ((const float*)wp)[8];
            acc[o][0] += wa.x * r00 + wa.z * r01 + wc.z * r10 + w8 * r11;
            acc[o][1] += wa.y * r01 + wc.w * r11;
            acc[o][2] += wa.w * r10 + wc.y * r11;
            acc[o][3] += wc.x * r11;
        }
    };

    const int nst = (C + ICB - 1) / ICB;
    stage_copy(0, 0, C < ICB ? C : ICB);
    cp_commit();
    for (int s = 0; s < nst; s++) {
        int buf = s & 1;
        cp_wait0();
        __syncthreads();
        int icn = (s + 1) * ICB;
        if (icn < C) {
            int cn = C - icn; if (cn > ICB) cn = ICB;
            stage_copy(buf ^ 1, icn, cn);
        }
        cp_commit();
        int cnt = C - s * ICB; if (cnt > ICB) cnt = ICB;
        if (cnt == ICB) {
#pragma unroll
            for (int j = 0; j < ICB; j++) compute_ch(buf, j);
        } else {
            for (int j = 0; j < cnt; j++) compute_ch(buf, j);
        }
    }

    float bv[4];
#pragma unroll
    for (int o = 0; o < 4; o++) bv[o] = bias[oc0 + g * 4 + o];
    unsigned* ob = out + (size_t)b * Hout * Wout * OC;
#pragma unroll
    for (int dy = 0; dy < 2; dy++)
#pragma unroll
        for (int dx = 0; dx < 2; dx++) {
            int y = y0 + 2 * ty + dy, x = x0 + 2 * tx + dx;
            uint4 p;
            float v0 = acc[0][dy * 2 + dx] + bv[0];
            float v1 = acc[1][dy * 2 + dx] + bv[1];
            float v2 = acc[2][dy * 2 + dx] + bv[2];
            float v3 = acc[3][dy * 2 + dx] + bv[3];
            p.x = pack_hl(v0 > 0.f ? v0 : 0.f);
            p.y = pack_hl(v1 > 0.f ? v1 : 0.f);
            p.z = pack_hl(v2 > 0.f ? v2 : 0.f);
            p.w = pack_hl(v3 > 0.f ? v3 : 0.f);
            *(uint4*)(ob + ((size_t)y * Wout + x) * OC + oc0 + g * 4) = p;
        }
}

// ---------------- keypoint bottleneck (packed NHWC R / maps) ----------------
__global__ void bn_stats(const unsigned* __restrict__ R, float* __restrict__ S,
                         float* __restrict__ Sh, float* __restrict__ Sw)
{
    int b = blockIdx.x;
    int k = threadIdx.x;     // 128
    const unsigned* Rb = R + (size_t)b * 256 * 128;
    float s = 0.f, sh = 0.f, sw = 0.f;
    for (int sp = 0; sp < 256; sp++) {
        float v = unpack_hl(Rb[sp * 128 + k]);
        s += v;
        sh += v * (float)(sp >> 4);
        sw += v * (float)(sp & 15);
    }
    S[b * 128 + k] = s;
    Sh[b * 128 + k] = sh;
    Sw[b * 128 + k] = sw;
}

__global__ void bn_maps(const float* __restrict__ S, const float* __restrict__ Sh,
                        const float* __restrict__ Sw, unsigned* __restrict__ maps)
{
    int b = blockIdx.x;
    int k = threadIdx.x;     // 128
    float s = S[b * 128 + k];
    float denom = S[b * 128 + 127];
    float mu = s * (1.f / 256.f);
    float inv = 1.f / denom;
    float c0 = Sh[b * 128 + k] * inv;
    float c1 = Sw[b * 128 + k] * inv;
    unsigned* mb = maps + (size_t)b * 256 * 128;
    for (int sp = 0; sp < 256; sp++) {
        float dh = (float)(sp >> 4) - c0;
        float dw = (float)(sp & 15) - c1;
        mb[sp * 128 + k] = pack_hl(mu * expf(-0.5f * (dh * dh + dw * dw)));
    }
}

// ---------------- launch ----------------
extern "C" void kernel_launch(void* const* d_in, const int* in_sizes, int n_in,
                              void* d_out, int out_size)
{
    (void)in_sizes; (void)n_in; (void)out_size;
    const float* x = (const float*)d_in[0];
    const float* ew[7]; const float* eb[7];
    for (int j = 0; j < 7; j++) {
        ew[j] = (const float*)d_in[1 + 2 * j];
        eb[j] = (const float*)d_in[2 + 2 * j];
    }
    const float* dw[6]; const float* db[6];
    for (int j = 0; j < 6; j++) {
        dw[j] = (const float*)d_in[15 + 2 * j];
        db[j] = (const float*)d_in[16 + 2 * j];
    }
    float* out = (float*)d_out;

    unsigned *buf0, *buf1;
    uint4* wprep;
    float *S, *Sh, *Sw;
    cudaGetSymbolAddress((void**)&buf0, g_buf0);
    cudaGetSymbolAddress((void**)&buf1, g_buf1);
    cudaGetSymbolAddress((void**)&wprep, g_wprep);
    cudaGetSymbolAddress((void**)&S, g_S);
    cudaGetSymbolAddress((void**)&Sh, g_Sh);
    cudaGetSymbolAddress((void**)&Sw, g_Sw);

    static bool attr_set = false;
    if (!attr_set) {
        cudaFuncSetAttribute(conv_mma_s1, cudaFuncAttributeMaxDynamicSharedMemorySize, MMA_SMEM);
        attr_set = true;
    }

    const int B = 32;
    // wprep offsets (uint4 units)
    const int OFF_E1 = 0, OFF_E3 = 2304, OFF_E5 = 11520;
    const int OFF_D1 = 48384, OFF_D3 = 57600, OFF_D5 = 59904;

    // ---- weight prep for mma layers ----
    prep_w<<<(2304 + 255) / 256, 256>>>(ew[1], wprep + OFF_E1, 32, 32);
    prep_w<<<(9216 + 255) / 256, 256>>>(ew[3], wprep + OFF_E3, 64, 64);
    prep_w<<<(36864 + 255) / 256, 256>>>(ew[5], wprep + OFF_E5, 128, 128);
    prep_w<<<(9216 + 255) / 256, 256>>>(dw[1], wprep + OFF_D1, 64, 64);
    prep_w<<<(2304 + 255) / 256, 256>>>(dw[3], wprep + OFF_D3, 32, 32);
    prep_w<<<(576 + 255) / 256, 256>>>(dw[5], wprep + OFF_D5, 16, 16);

    // ---- encoder ----
    conv_e0<<<dim3(32, 1, B), 256>>>(x, ew[0], eb[0], buf0, 3, 32, 128, 128, 0);
    conv_mma_s1<<<dim3(64, 1, B), 256, MMA_SMEM>>>(buf0, wprep + OFF_E1, eb[1], buf1,
                                                   32, 32, 128, 128, 0, 0);
    conv_s2<32><<<dim3(16, 2, B), 256>>>(buf1, ew[2], eb[2], buf0, 32, 64, 64, 64, 1);
    conv_mma_s1<<<dim3(16, 2, B), 256, MMA_SMEM>>>(buf0, wprep + OFF_E3, eb[3], buf1,
                                                   64, 64, 64, 64, 1, 0);
    conv_s2<32><<<dim3(4, 4, B), 256>>>(buf1, ew[4], eb[4], buf0, 64, 128, 32, 32, 1);
    conv_mma_s1<<<dim3(4, 4, B), 256, MMA_SMEM>>>(buf0, wprep + OFF_E5, eb[5], buf1,
                                                  128, 128, 32, 32, 1, 0);
    conv_s2<8><<<dim3(1, 16, B), 64>>>(buf1, ew[6], eb[6], buf0, 128, 128, 16, 16, 3);
    // ---- keypoint bottleneck ----
    bn_stats<<<32, 128>>>(buf0, S, Sh, Sw);
    bn_maps<<<32, 128>>>(S, Sh, Sw, buf1);
    // ---- decoder ----
    tconv_s2<<<dim3(4, 4, B), 256>>>(buf1, dw[0], db[0], buf0, 128, 64, 32, 32);
    conv_mma_s1<<<dim3(4, 2, B), 256, MMA_SMEM>>>(buf0, wprep + OFF_D1, db[1], buf1,
                                                  64, 64, 32, 32, 2, 0);
    tconv_s2<<<dim3(16, 2, B), 256>>>(buf1, dw[2], db[2], buf0, 64, 32, 64, 64);
    conv_mma_s1<<<dim3(16, 1, B), 256, MMA_SMEM>>>(buf0, wprep + OFF_D3, db[3], buf1,
                                                   32, 32, 64, 64, 2, 0);
    tconv_s2<<<dim3(64, 1, B), 256>>>(buf1, dw[4], db[4], buf0, 32, 16, 128, 128);
    conv_mma_s1<<<dim3(64, 1, B), 256, MMA_SMEM>>>(buf0, wprep + OFF_D5, db[5], out,
                                                   16, 16, 128, 128, 2, 1);
}

// round 5
// speedup vs baseline: 1.8090x; 1.0139x over previous
#include <cuda_runtime.h>
#include <cuda_bf16.h>
#include <math.h>

// ---------------- scratch (allocation-free: __device__ globals) ----------------
__device__ float g_f0[32u * 32 * 128 * 128];            // fp32 NHWC ping
__device__ float g_f1[32u * 32 * 128 * 128];            // fp32 NHWC pong
__device__ unsigned short g_bf[2u * 32 * 32 * 128 * 128]; // dual bf16 planes [px][2C]
__device__ uint4 g_wprep[60480];
__device__ float g_S[4096];
__device__ float g_Sh[4096];
__device__ float g_Sw[4096];

__device__ __forceinline__ float activate(float v, int act) {
    switch (act) {
        case 1: return v > 0.f ? v : 0.2f * v;
        case 2: return v > 0.f ? v : 0.f;
        case 3: return fmaxf(v, 0.f) + log1pf(expf(-fabsf(v)));
        default: return v;
    }
}

__device__ __forceinline__ void split_bf16(float x, unsigned short& h, unsigned short& l) {
    h = __bfloat16_as_ushort(__float2bfloat16(x));
    float hf = __uint_as_float((unsigned)h << 16);
    l = __bfloat16_as_ushort(__float2bfloat16(x - hf));
}
__device__ __forceinline__ unsigned pack_us(unsigned short a, unsigned short b) {
    return ((unsigned)b << 16) | (unsigned)a;
}
__device__ __forceinline__ unsigned pack2_bf16(float e_lo, float e_hi) {
    return ((unsigned)__bfloat16_as_ushort(__float2bfloat16(e_hi)) << 16)
         | (unsigned)__bfloat16_as_ushort(__float2bfloat16(e_lo));
}

__device__ __forceinline__ void cp_async4(void* sdst, const void* gsrc, bool pred) {
    unsigned saddr = (unsigned)__cvta_generic_to_shared(sdst);
    int sz = pred ? 4 : 0;
    asm volatile("cp.async.ca.shared.global [%0], [%1], 4, %2;\n"
                 :: "r"(saddr), "l"(gsrc), "r"(sz));
}
__device__ __forceinline__ void cp_async16(void* sdst, const void* gsrc, bool pred) {
    unsigned saddr = (unsigned)__cvta_generic_to_shared(sdst);
    int sz = pred ? 16 : 0;
    asm volatile("cp.async.cg.shared.global [%0], [%1], 16, %2;\n"
                 :: "r"(saddr), "l"(gsrc), "r"(sz));
}
__device__ __forceinline__ void cp_commit() { asm volatile("cp.async.commit_group;\n"); }
__device__ __forceinline__ void cp_wait0() { asm volatile("cp.async.wait_group 0;\n"); }

__device__ __forceinline__ void mma16816(float* d, const unsigned* a, unsigned b0, unsigned b1) {
    asm volatile("mma.sync.aligned.m16n8k16.row.col.f32.bf16.bf16.f32 "
                 "{%0,%1,%2,%3},{%4,%5,%6,%7},{%8,%9},{%0,%1,%2,%3};"
                 : "+f"(d[0]), "+f"(d[1]), "+f"(d[2]), "+f"(d[3])
                 : "r"(a[0]), "r"(a[1]), "r"(a[2]), "r"(a[3]), "r"(b0), "r"(b1));
}

// =====================================================================
// weight prep (3 layers per launch): OIHW fp32 -> hi/lo bf16x2 fragments
// layout [(kc*9 + t)*(OC/8) + og]*32 + lane, uint4 = (b0h, b1h, b0l, b1l)
// =====================================================================
__global__ void prep_many(const float* __restrict__ w0, const float* __restrict__ w1,
                          const float* __restrict__ w2, uint4* __restrict__ dstb,
                          int off0, int off1, int off2,
                          int C0, int OC0, int C1, int OC1, int C2, int OC2)
{
    int layer = blockIdx.y;
    const float* w = layer == 0 ? w0 : layer == 1 ? w1 : w2;
    uint4* dst = dstb + (layer == 0 ? off0 : layer == 1 ? off1 : off2);
    int C = layer == 0 ? C0 : layer == 1 ? C1 : C2;
    int OC = layer == 0 ? OC0 : layer == 1 ? OC1 : OC2;
    int OCg = OC >> 3;
    int total = (C >> 4) * 9 * OCg * 32;
    int idx = blockIdx.x * 256 + threadIdx.x;
    if (idx >= total) return;
    int l = idx & 31;
    int q = idx >> 5;
    int og = q % OCg; q /= OCg;
    int t = q % 9;
    int kc = q / 9;
    int tg = l & 3, gg = l >> 2;
    int n = og * 8 + gg;
    float h[4], lo[4];
#pragma unroll
    for (int kk = 0; kk < 4; kk++) {
        int k = (kk < 2) ? (2 * tg + kk) : (2 * tg + 8 + (kk - 2));
        int ic = (kc << 4) + k;
        float e = w[((size_t)n * C + ic) * 9 + t];
        unsigned hb = (unsigned)__bfloat16_as_ushort(__float2bfloat16(e)) << 16;
        h[kk] = __uint_as_float(hb);
        lo[kk] = e - h[kk];
    }
    uint4 r;
    r.x = pack2_bf16(h[0], h[1]);
    r.y = pack2_bf16(h[2], h[3]);
    r.z = pack2_bf16(lo[0], lo[1]);
    r.w = pack2_bf16(lo[2], lo[3]);
    dst[idx] = r;
}

// =====================================================================
// tensor-core stride-1 3x3 SAME conv (bf16x3 split, fp32 accum).
// block: 16x16 px tile x 32 oc. input: dual bf16 planes. output: fp32.
// =====================================================================
#define SINW (324 * 12)
#define MMA_SW (9 * 4 * 32)
#define MMA_SMEM (2 * 2 * SINW * 4 + 2 * MMA_SW * 16)

__global__ void __launch_bounds__(256, 2) conv_mma_s1(
    const unsigned short* __restrict__ in, const uint4* __restrict__ wp,
    const float* __restrict__ bias, float* __restrict__ outp,
    int C, int OC, int H, int W, int act, int nchwout)
{
    const int KC = C >> 4;
    const int tilesX = W >> 4;
    const int x0 = (blockIdx.x % tilesX) << 4;
    const int y0 = (blockIdx.x / tilesX) << 4;
    const int oc0 = blockIdx.y << 5;
    const int b = blockIdx.z;
    const int OCg = OC >> 3;
    int nf = OCg - (oc0 >> 3); if (nf > 4) nf = 4;

    extern __shared__ __align__(16) unsigned char dsm[];
    unsigned* s_hi = (unsigned*)dsm;                    // [2][SINW]
    unsigned* s_lo = s_hi + 2 * SINW;                   // [2][SINW]
    uint4* s_w = (uint4*)(dsm + 4 * 4 * SINW);          // [2][MMA_SW]

    const unsigned short* inb = in + (size_t)b * H * W * 2 * C;
    const int tid = threadIdx.x, lane = tid & 31, wid = tid >> 5;
    const int g = lane >> 2, tg = lane & 3;

    float d[2][4][4];
#pragma unroll
    for (int i = 0; i < 2; i++)
#pragma unroll
        for (int j = 0; j < 4; j++)
#pragma unroll
            for (int r = 0; r < 4; r++) d[i][j][r] = 0.f;

    auto stage = [&](int buf, int kc) {
        unsigned* hi = s_hi + buf * SINW;
        unsigned* lo = s_lo + buf * SINW;
        for (int i = tid; i < 648; i += 256) {
            int sp = i >> 1, q = i & 1;
            int r = sp / 18, c = sp - r * 18;
            int iy = y0 - 1 + r, ix = x0 - 1 + c;
            bool p = (unsigned)iy < (unsigned)H && (unsigned)ix < (unsigned)W;
            const unsigned short* src = inb + ((size_t)iy * W + ix) * 2 * C + (kc << 4) + (q << 3);
            cp_async16(hi + sp * 12 + q * 4, src, p);
            cp_async16(lo + sp * 12 + q * 4, src + C, p);
        }
        uint4* sw = s_w + buf * MMA_SW;
        const uint4* wsrc = wp + (size_t)kc * 9 * OCg * 32;
        int tot = 9 * nf * 32;
        for (int i = tid; i < tot; i += 256) {
            int l = i & 31;
            int q = i >> 5;
            int ogl = q % nf;
            int t = q / nf;
            cp_async16(sw + (t * 4 + ogl) * 32 + l,
                       wsrc + ((size_t)t * OCg + (oc0 >> 3) + ogl) * 32 + l, true);
        }
    };

    auto compute = [&](int buf) {
        unsigned* hi = s_hi + buf * SINW;
        unsigned* lo = s_lo + buf * SINW;
        uint4* sw = s_w + buf * MMA_SW;
#pragma unroll
        for (int t = 0; t < 9; t++) {
            const int dy = t / 3, dx = t - 3 * (t / 3);
            unsigned ah[2][4], al[2][4];
#pragma unroll
            for (int i = 0; i < 2; i++) {
                int sp0 = (2 * wid + i + dy) * 18 + g + dx;
                const unsigned* h0 = hi + sp0 * 12;
                const unsigned* l0 = lo + sp0 * 12;
                ah[i][0] = h0[tg];       ah[i][1] = h0[96 + tg];
                ah[i][2] = h0[tg + 4];   ah[i][3] = h0[96 + tg + 4];
                al[i][0] = l0[tg];       al[i][1] = l0[96 + tg];
                al[i][2] = l0[tg + 4];   al[i][3] = l0[96 + tg + 4];
            }
            for (int j = 0; j < nf; j++) {
                uint4 bw = sw[(t * 4 + j) * 32 + lane];
#pragma unroll
                for (int i = 0; i < 2; i++) {
                    mma16816(d[i][j], ah[i], bw.x, bw.y);   // hi*hi
                    mma16816(d[i][j], al[i], bw.x, bw.y);   // lo*hi
                    mma16816(d[i][j], ah[i], bw.z, bw.w);   // hi*lo
                }
            }
        }
    };

    stage(0, 0);
    cp_commit();
    for (int kc = 0; kc < KC; kc++) {
        int buf = kc & 1;
        cp_wait0();
        __syncthreads();
        if (kc + 1 < KC) stage(buf ^ 1, kc + 1);
        cp_commit();
        compute(buf);
    }

    // epilogue: rows(x)=g/g+8, cols(oc)=8j+2tg(+1); y=y0+2*wid+i
    if (!nchwout) {
        float* ob = outp + (size_t)b * H * W * OC;
#pragma unroll
        for (int i = 0; i < 2; i++) {
            int y = y0 + 2 * wid + i;
            for (int j = 0; j < nf; j++) {
                int oc = oc0 + 8 * j + 2 * tg;
                float b0 = bias[oc], b1 = bias[oc + 1];
                float2 v0, v1;
                v0.x = activate(d[i][j][0] + b0, act);
                v0.y = activate(d[i][j][1] + b1, act);
                v1.x = activate(d[i][j][2] + b0, act);
                v1.y = activate(d[i][j][3] + b1, act);
                *(float2*)(ob + ((size_t)y * W + x0 + g) * OC + oc) = v0;
                *(float2*)(ob + ((size_t)y * W + x0 + g + 8) * OC + oc) = v1;
            }
        }
    } else {
        float* of = outp;
#pragma unroll
        for (int i = 0; i < 2; i++) {
            int y = y0 + 2 * wid + i;
            for (int j = 0; j < nf; j++) {
                int oc = oc0 + 8 * j + 2 * tg;
                float b0 = bias[oc], b1 = bias[oc + 1];
                size_t base0 = (((size_t)b * OC + oc) * H + y) * W + x0;
                size_t base1 = base0 + (size_t)H * W;
                of[base0 + g]     = activate(d[i][j][0] + b0, act);
                of[base1 + g]     = activate(d[i][j][1] + b1, act);
                of[base0 + g + 8] = activate(d[i][j][2] + b0, act);
                of[base1 + g + 8] = activate(d[i][j][3] + b1, act);
            }
        }
    }
}

// dual-format epilogue helper: write fp32 NHWC + bf16 hi/lo planes
__device__ __forceinline__ void store_dual8(float* fout, unsigned short* bout,
                                            size_t px, int OC, int ocbase,
                                            const float* v)
{
    float* f = fout + px * OC + ocbase;
    *(float4*)f = make_float4(v[0], v[1], v[2], v[3]);
    *(float4*)(f + 4) = make_float4(v[4], v[5], v[6], v[7]);
    unsigned short h[8], l[8];
#pragma unroll
    for (int o = 0; o < 8; o++) split_bf16(v[o], h[o], l[o]);
    unsigned short* bb = bout + px * 2 * OC + ocbase;
    uint4 H, L;
    H.x = pack_us(h[0], h[1]); H.y = pack_us(h[2], h[3]);
    H.z = pack_us(h[4], h[5]); H.w = pack_us(h[6], h[7]);
    L.x = pack_us(l[0], l[1]); L.y = pack_us(l[2], l[3]);
    L.z = pack_us(l[4], l[5]); L.w = pack_us(l[6], l[7]);
    *(uint4*)bb = H;
    *(uint4*)(bb + OC) = L;
}

// =====================================================================
// e0 scalar conv: fp32 NCHW input (C=3) -> fp32 NHWC + dual bf16.
// =====================================================================
__global__ void __launch_bounds__(256, 2) conv_e0(
    const float* __restrict__ in, const float* __restrict__ wgt,
    const float* __restrict__ bias, float* __restrict__ fout,
    unsigned short* __restrict__ bout, int C, int OC, int H, int W, int act)
{
    constexpr int NT = 256;
    constexpr int ICB = 4;
    constexpr int SROW = 34;
    constexpr int SIN = 18 * SROW;

    const int tilesX = W >> 5;
    const int x0 = (blockIdx.x % tilesX) << 5;
    const int y0 = (blockIdx.x / tilesX) << 4;
    const int oc0 = blockIdx.y * 32;
    const int b = blockIdx.z;

    __shared__ __align__(16) float s_in[2][ICB][SIN];
    __shared__ __align__(16) float s_w[2][ICB][32 * 12];

    const int tid = threadIdx.x;
    const int g = tid >> 6;
    const int sp = tid & 63;
    const int ty = sp >> 3, tx = sp & 7;

    float acc[8][2][4];
#pragma unroll
    for (int o = 0; o < 8; o++)
#pragma unroll
        for (int dy = 0; dy < 2; dy++)
#pragma unroll
            for (int dx = 0; dx < 4; dx++) acc[o][dy][dx] = 0.f;

    const float* inb = in + (size_t)b * C * H * W;
    const float* wb = wgt + (size_t)oc0 * C * 9;

    auto stage_copy = [&](int buf, int ic0, int cnt) {
        const float* ins = inb + (size_t)ic0 * H * W;
        for (int i = tid; i < cnt * SIN; i += NT) {
            int ch = i / SIN, r2 = i - ch * SIN;
            int r = r2 / SROW, c2 = r2 - r * SROW;
            int iy = y0 - 1 + r, ix = x0 - 1 + c2;
            bool p = (unsigned)iy < (unsigned)H && (unsigned)ix < (unsigned)W;
            cp_async4(&s_in[buf][ch][r2], ins + (size_t)ch * H * W + (size_t)iy * W + ix, p);
        }
        for (int i = tid; i < cnt * 32 * 9; i += NT) {
            int ch = i / (32 * 9), r2 = i - ch * (32 * 9);
            int o = r2 / 9, j2 = r2 - o * 9;
            cp_async4(&s_w[buf][ch][o * 12 + j2],
                      wb + ((size_t)o * C + ic0 + ch) * 9 + j2, true);
        }
    };

    const int sbase = (2 * ty) * SROW + 4 * tx;

    auto compute_ch = [&](int buf, int ch) {
        float rr[4][6];
        const float* si = &s_in[buf][ch][sbase];
#pragma unroll
        for (int r = 0; r < 4; r++) {
            const float2* p = (const float2*)(si + r * SROW);
            float2 a = p[0], b2 = p[1], c2 = p[2];
            rr[r][0] = a.x; rr[r][1] = a.y; rr[r][2] = b2.x;
            rr[r][3] = b2.y; rr[r][4] = c2.x; rr[r][5] = c2.y;
        }
#pragma unroll
        for (int o = 0; o < 8; o++) {
            const float4* wp = (const float4*)&s_w[buf][ch][(g * 8 + o) * 12];
            float4 wa = wp[0];
            float4 wc = wp[1];
            float w8 = ((const float*)wp)[8];
#pragma unroll
            for (int dy = 0; dy < 2; dy++)
#pragma unroll
                for (int dx = 0; dx < 4; dx++) {
                    float s = acc[o][dy][dx];
                    s += wa.x * rr[dy + 0][dx + 0];
                    s += wa.y * rr[dy + 0][dx + 1];
                    s += wa.z * rr[dy + 0][dx + 2];
                    s += wa.w * rr[dy + 1][dx + 0];
                    s += wc.x * rr[dy + 1][dx + 1];
                    s += wc.y * rr[dy + 1][dx + 2];
                    s += wc.z * rr[dy + 2][dx + 0];
                    s += wc.w * rr[dy + 2][dx + 1];
                    s += w8   * rr[dy + 2][dx + 2];
                    acc[o][dy][dx] = s;
                }
        }
    };

    const int nst = (C + ICB - 1) / ICB;
    stage_copy(0, 0, C < ICB ? C : ICB);
    cp_commit();
    for (int s = 0; s < nst; s++) {
        int buf = s & 1;
        cp_wait0();
        __syncthreads();
        int icn = (s + 1) * ICB;
        if (icn < C) {
            int cn = C - icn; if (cn > ICB) cn = ICB;
            stage_copy(buf ^ 1, icn, cn);
        }
        cp_commit();
        int cnt = C - s * ICB; if (cnt > ICB) cnt = ICB;
        for (int j = 0; j < cnt; j++) compute_ch(buf, j);
    }

    float bv[8];
#pragma unroll
    for (int o = 0; o < 8; o++) bv[o] = bias[oc0 + g * 8 + o];
    float* fo = fout + (size_t)b * H * W * OC;
    unsigned short* bo = bout + (size_t)b * H * W * 2 * OC;
#pragma unroll
    for (int dy = 0; dy < 2; dy++)
#pragma unroll
        for (int dx = 0; dx < 4; dx++) {
            int y = y0 + 2 * ty + dy, x = x0 + 4 * tx + dx;
            float v[8];
#pragma unroll
            for (int o = 0; o < 8; o++) v[o] = activate(acc[o][dy][dx] + bv[o], act);
            store_dual8(fo, bo, (size_t)y * W + x, OC, oc0 + g * 8, v);
        }
}

// =====================================================================
// stride-2 3x3 SAME conv (pad lo=0, hi=1). fp32 NHWC in -> dual out.
// =====================================================================
template <int OCB>
__global__ void __launch_bounds__(64 * (OCB / 8), 512 / (64 * (OCB / 8))) conv_s2(
    const float* __restrict__ in, const float* __restrict__ wgt,
    const float* __restrict__ bias, float* __restrict__ fout,
    unsigned short* __restrict__ bout, int C, int OC, int Hout, int Wout, int act)
{
    constexpr int NT = 64 * (OCB / 8);
    constexpr int ICB = 4;
    constexpr int SIN = 33 * 33;

    const int Hin = Hout * 2, Win = Wout * 2;
    const int tilesX = Wout >> 4;
    const int x0 = (blockIdx.x % tilesX) << 4;
    const int y0 = (blockIdx.x / tilesX) << 4;
    const int oc0 = blockIdx.y * OCB;
    const int b = blockIdx.z;

    __shared__ __align__(16) float s_in[2][ICB][SIN + 1];
    __shared__ __align__(16) float s_w[2][ICB][OCB * 12];

    const int tid = threadIdx.x;
    const int g = tid >> 6;
    const int sp = tid & 63;
    const int ty = sp >> 3, tx = sp & 7;

    float acc[8][4];
#pragma unroll
    for (int o = 0; o < 8; o++)
#pragma unroll
        for (int p = 0; p < 4; p++) acc[o][p] = 0.f;

    const float* inb = in + (size_t)b * Hin * Win * C;
    const float* wb = wgt + (size_t)oc0 * C * 9;

    auto stage_copy = [&](int buf, int ic0, int cnt) {
        for (int i = tid; i < cnt * SIN; i += NT) {
            int ch = i / SIN, r2 = i - ch * SIN;
            int r = r2 / 33, c2 = r2 - r * 33;
            int iy = 2 * y0 + r, ix = 2 * x0 + c2;
            bool p = iy < Hin && ix < Win;
            cp_async4(&s_in[buf][ch][r2],
                      inb + ((size_t)iy * Win + ix) * C + ic0 + ch, p);
        }
        for (int i = tid; i < cnt * OCB * 9; i += NT) {
            int ch = i / (OCB * 9), r2 = i - ch * (OCB * 9);
            int o = r2 / 9, j2 = r2 - o * 9;
            cp_async4(&s_w[buf][ch][o * 12 + j2],
                      wb + ((size_t)o * C + ic0 + ch) * 9 + j2, true);
        }
    };

    auto compute_ch = [&](int buf, int ch) {
        float rr[5][5];
#pragma unroll
        for (int r = 0; r < 5; r++)
#pragma unroll
            for (int c = 0; c < 5; c++)
                rr[r][c] = s_in[buf][ch][(4 * ty + r) * 33 + 4 * tx + c];
#pragma unroll
        for (int o = 0; o < 8; o++) {
            const float4* wp = (const float4*)&s_w[buf][ch][(g * 8 + o) * 12];
            float4 wa = wp[0];
            float4 wc = wp[1];
            float w8 = ((const float*)wp)[8];
#pragma unroll
            for (int dy = 0; dy < 2; dy++)
#pragma unroll
                for (int dx = 0; dx < 2; dx++) {
                    float s = acc[o][dy * 2 + dx];
                    s += wa.x * rr[2 * dy + 0][2 * dx + 0];
                    s += wa.y * rr[2 * dy + 0][2 * dx + 1];
                    s += wa.z * rr[2 * dy + 0][2 * dx + 2];
                    s += wa.w * rr[2 * dy + 1][2 * dx + 0];
                    s += wc.x * rr[2 * dy + 1][2 * dx + 1];
                    s += wc.y * rr[2 * dy + 1][2 * dx + 2];
                    s += wc.z * rr[2 * dy + 2][2 * dx + 0];
                    s += wc.w * rr[2 * dy + 2][2 * dx + 1];
                    s += w8   * rr[2 * dy + 2][2 * dx + 2];
                    acc[o][dy * 2 + dx] = s;
                }
        }
    };

    const int nst = (C + ICB - 1) / ICB;
    stage_copy(0, 0, C < ICB ? C : ICB);
    cp_commit();
    for (int s = 0; s < nst; s++) {
        int buf = s & 1;
        cp_wait0();
        __syncthreads();
        int icn = (s + 1) * ICB;
        if (icn < C) {
            int cn = C - icn; if (cn > ICB) cn = ICB;
            stage_copy(buf ^ 1, icn, cn);
        }
        cp_commit();
        int cnt = C - s * ICB; if (cnt > ICB) cnt = ICB;
        if (cnt == ICB) {
#pragma unroll
            for (int j = 0; j < ICB; j++) compute_ch(buf, j);
        } else {
            for (int j = 0; j < cnt; j++) compute_ch(buf, j);
        }
    }

    float bv[8];
#pragma unroll
    for (int o = 0; o < 8; o++) bv[o] = bias[oc0 + g * 8 + o];
    float* fo = fout + (size_t)b * Hout * Wout * OC;
    unsigned short* bo = bout + (size_t)b * Hout * Wout * 2 * OC;
#pragma unroll
    for (int dy = 0; dy < 2; dy++)
#pragma unroll
        for (int dx = 0; dx < 2; dx++) {
            int y = y0 + 2 * ty + dy, x = x0 + 2 * tx + dx;
            float v[8];
#pragma unroll
            for (int o = 0; o < 8; o++) v[o] = activate(acc[o][dy * 2 + dx] + bv[o], act);
            store_dual8(fo, bo, (size_t)y * Wout + x, OC, oc0 + g * 8, v);
        }
}

// =====================================================================
// transposed conv 3x3 stride-2 SAME (pad_a=2). fp32 in -> dual out. relu.
// =====================================================================
__global__ void __launch_bounds__(256, 3) tconv_s2(
    const float* __restrict__ in, const float* __restrict__ wgt,
    const float* __restrict__ bias, float* __restrict__ fout,
    unsigned short* __restrict__ bout, int C, int OC, int Hout, int Wout)
{
    constexpr int NT = 256;
    constexpr int ICB = 4;
    constexpr int SIN = 9 * 9;

    const int Hin = Hout >> 1, Win = Wout >> 1;
    const int tilesX = Wout >> 4;
    const int x0 = (blockIdx.x % tilesX) << 4;
    const int y0 = (blockIdx.x / tilesX) << 4;
    const int oc0 = blockIdx.y * 16;
    const int b = blockIdx.z;
    const int Y0 = y0 >> 1, X0 = x0 >> 1;

    __shared__ __align__(16) float s_in[2][ICB][SIN + 3];
    __shared__ __align__(16) float s_w[2][ICB][16 * 12];

    const int tid = threadIdx.x;
    const int g = tid >> 6;
    const int sp = tid & 63;
    const int ty = sp >> 3, tx = sp & 7;

    float acc[4][4];
#pragma unroll
    for (int o = 0; o < 4; o++)
#pragma unroll
        for (int p = 0; p < 4; p++) acc[o][p] = 0.f;

    const float* inb = in + (size_t)b * Hin * Win * C;
    const float* wb = wgt + (size_t)oc0 * C * 9;

    auto stage_copy = [&](int buf, int ic0, int cnt) {
        for (int i = tid; i < cnt * SIN; i += NT) {
            int ch = i / SIN, r2 = i - ch * SIN;
            int r = r2 / 9, c2 = r2 - r * 9;
            int iy = Y0 - 1 + r, ix = X0 - 1 + c2;
            bool p = (unsigned)iy < (unsigned)Hin && (unsigned)ix < (unsigned)Win;
            cp_async4(&s_in[buf][ch][r2],
                      inb + ((size_t)iy * Win + ix) * C + ic0 + ch, p);
        }
        for (int i = tid; i < cnt * 16 * 9; i += NT) {
            int ch = i / (16 * 9), r2 = i - ch * (16 * 9);
            int o = r2 / 9, j2 = r2 - o * 9;
            cp_async4(&s_w[buf][ch][o * 12 + j2],
                      wb + ((size_t)o * C + ic0 + ch) * 9 + j2, true);
        }
    };

    auto compute_ch = [&](int buf, int ch) {
        const float* si = s_in[buf][ch];
        float r00 = si[ty * 9 + tx];
        float r01 = si[ty * 9 + tx + 1];
        float r10 = si[(ty + 1) * 9 + tx];
        float r11 = si[(ty + 1) * 9 + tx + 1];
#pragma unroll
        for (int o = 0; o < 4; o++) {
            const float4* wp = (const float4*)&s_w[buf][ch][(g * 4 + o) * 12];
            float4 wa = wp[0];
            float4 wc = wp[1];
            float w8 = ((const float*)wp)[8];
            acc[o][0] += wa.x * r00 + wa.z * r01 + wc.z * r10 + w8 * r11;
            acc[o][1] += wa.y * r01 + wc.w * r11;
            acc[o][2] += wa.w * r10 + wc.y * r11;
            acc[o][3] += wc.x * r11;
        }
    };

    const int nst = (C + ICB - 1) / ICB;
    stage_copy(0, 0, C < ICB ? C : ICB);
    cp_commit();
    for (int s = 0; s < nst; s++) {
        int buf = s & 1;
        cp_wait0();
        __syncthreads();
        int icn = (s + 1) * ICB;
        if (icn < C) {
            int cn = C - icn; if (cn > ICB) cn = ICB;
            stage_copy(buf ^ 1, icn, cn);
        }
        cp_commit();
        int cnt = C - s * ICB; if (cnt > ICB) cnt = ICB;
        if (cnt == ICB) {
#pragma unroll
            for (int j = 0; j < ICB; j++) compute_ch(buf, j);
        } else {
            for (int j = 0; j < cnt; j++) compute_ch(buf, j);
        }
    }

    float bv[4];
#pragma unroll
    for (int o = 0; o < 4; o++) bv[o] = bias[oc0 + g * 4 + o];
    float* fo = fout + (size_t)b * Hout * Wout * OC;
    unsigned short* bo = bout + (size_t)b * Hout * Wout * 2 * OC;
#pragma unroll
    for (int dy = 0; dy < 2; dy++)
#pragma unroll
        for (int dx = 0; dx < 2; dx++) {
            int y = y0 + 2 * ty + dy, x = x0 + 2 * tx + dx;
            size_t px = (size_t)y * Wout + x;
            float v[4];
#pragma unroll
            for (int o = 0; o < 4; o++) {
                float t = acc[o][dy * 2 + dx] + bv[o];
                v[o] = t > 0.f ? t : 0.f;
            }
            *(float4*)(fo + px * OC + oc0 + g * 4) = make_float4(v[0], v[1], v[2], v[3]);
            unsigned short h[4], l[4];
#pragma unroll
            for (int o = 0; o < 4; o++) split_bf16(v[o], h[o], l[o]);
            unsigned short* bb = bo + px * 2 * OC + oc0 + g * 4;
            *(uint2*)bb = make_uint2(pack_us(h[0], h[1]), pack_us(h[2], h[3]));
            *(uint2*)(bb + OC) = make_uint2(pack_us(l[0], l[1]), pack_us(l[2], l[3]));
        }
}

// ---------------- keypoint bottleneck (fp32 NHWC) ----------------
__global__ void bn_stats(const float* __restrict__ R, float* __restrict__ S,
                         float* __restrict__ Sh, float* __restrict__ Sw)
{
    int b = blockIdx.x;
    int k = threadIdx.x;     // 128
    const float* Rb = R + (size_t)b * 256 * 128;
    float s = 0.f, sh = 0.f, sw = 0.f;
    for (int sp = 0; sp < 256; sp++) {
        float v = Rb[sp * 128 + k];
        s += v;
        sh += v * (float)(sp >> 4);
        sw += v * (float)(sp & 15);
    }
    S[b * 128 + k] = s;
    Sh[b * 128 + k] = sh;
    Sw[b * 128 + k] = sw;
}

__global__ void bn_maps(const float* __restrict__ S, const float* __restrict__ Sh,
                        const float* __restrict__ Sw, float* __restrict__ maps)
{
    int b = blockIdx.x;
    int k = threadIdx.x;     // 128
    float s = S[b * 128 + k];
    float denom = S[b * 128 + 127];
    float mu = s * (1.f / 256.f);
    float inv = 1.f / denom;
    float c0 = Sh[b * 128 + k] * inv;
    float c1 = Sw[b * 128 + k] * inv;
    float* mb = maps + (size_t)b * 256 * 128;
    for (int sp = 0; sp < 256; sp++) {
        float dh = (float)(sp >> 4) - c0;
        float dw = (float)(sp & 15) - c1;
        mb[sp * 128 + k] = mu * expf(-0.5f * (dh * dh + dw * dw));
    }
}

// ---------------- launch ----------------
extern "C" void kernel_launch(void* const* d_in, const int* in_sizes, int n_in,
                              void* d_out, int out_size)
{
    (void)in_sizes; (void)n_in; (void)out_size;
    const float* x = (const float*)d_in[0];
    const float* ew[7]; const float* eb[7];
    for (int j = 0; j < 7; j++) {
        ew[j] = (const float*)d_in[1 + 2 * j];
        eb[j] = (const float*)d_in[2 + 2 * j];
    }
    const float* dw[6]; const float* db[6];
    for (int j = 0; j < 6; j++) {
        dw[j] = (const float*)d_in[15 + 2 * j];
        db[j] = (const float*)d_in[16 + 2 * j];
    }
    float* out = (float*)d_out;

    float *F0, *F1, *S, *Sh, *Sw;
    unsigned short* B0;
    uint4* wprep;
    cudaGetSymbolAddress((void**)&F0, g_f0);
    cudaGetSymbolAddress((void**)&F1, g_f1);
    cudaGetSymbolAddress((void**)&B0, g_bf);
    cudaGetSymbolAddress((void**)&wprep, g_wprep);
    cudaGetSymbolAddress((void**)&S, g_S);
    cudaGetSymbolAddress((void**)&Sh, g_Sh);
    cudaGetSymbolAddress((void**)&Sw, g_Sw);

    static bool attr_set = false;
    if (!attr_set) {
        cudaFuncSetAttribute(conv_mma_s1, cudaFuncAttributeMaxDynamicSharedMemorySize, MMA_SMEM);
        attr_set = true;
    }

    const int B = 32;
    const int OFF_E1 = 0, OFF_E3 = 2304, OFF_E5 = 11520;
    const int OFF_D1 = 48384, OFF_D3 = 57600, OFF_D5 = 59904;

    // 1: encoder weight prep (e1, e3, e5)
    prep_many<<<dim3(144, 3, 1), 256>>>(ew[1], ew[3], ew[5], wprep,
                                        OFF_E1, OFF_E3, OFF_E5, 32, 32, 64, 64, 128, 128);
    // 2: e0
    conv_e0<<<dim3(32, 1, B), 256>>>(x, ew[0], eb[0], F0, B0, 3, 32, 128, 128, 0);
    // 3: e1 (mma)
    conv_mma_s1<<<dim3(64, 1, B), 256, MMA_SMEM>>>(B0, wprep + OFF_E1, eb[1], F1,
                                                   32, 32, 128, 128, 0, 0);
    // 4: e2 (s2)
    conv_s2<32><<<dim3(16, 2, B), 256>>>(F1, ew[2], eb[2], F0, B0, 32, 64, 64, 64, 1);
    // 5: decoder weight prep (d1, d3, d5)
    prep_many<<<dim3(36, 3, 1), 256>>>(dw[1], dw[3], dw[5], wprep,
                                       OFF_D1, OFF_D3, OFF_D5, 64, 64, 32, 32, 16, 16);
    // 6: e3 (mma)  <-- ncu -s 5 -c 1 profiles this launch
    conv_mma_s1<<<dim3(16, 2, B), 256, MMA_SMEM>>>(B0, wprep + OFF_E3, eb[3], F1,
                                                   64, 64, 64, 64, 1, 0);
    conv_s2<32><<<dim3(4, 4, B), 256>>>(F1, ew[4], eb[4], F0, B0, 64, 128, 32, 32, 1);
    conv_mma_s1<<<dim3(4, 4, B), 256, MMA_SMEM>>>(B0, wprep + OFF_E5, eb[5], F1,
                                                  128, 128, 32, 32, 1, 0);
    conv_s2<8><<<dim3(1, 16, B), 64>>>(F1, ew[6], eb[6], F0, B0, 128, 128, 16, 16, 3);
    // ---- keypoint bottleneck ----
    bn_stats<<<32, 128>>>(F0, S, Sh, Sw);
    bn_maps<<<32, 128>>>(S, Sh, Sw, F1);
    // ---- decoder ----
    tconv_s2<<<dim3(4, 4, B), 256>>>(F1, dw[0], db[0], F0, B0, 128, 64, 32, 32);
    conv_mma_s1<<<dim3(4, 2, B), 256, MMA_SMEM>>>(B0, wprep + OFF_D1, db[1], F1,
                                                  64, 64, 32, 32, 2, 0);
    tconv_s2<<<dim3(16, 2, B), 256>>>(F1, dw[2], db[2], F0, B0, 64, 32, 64, 64);
    conv_mma_s1<<<dim3(16, 1, B), 256, MMA_SMEM>>>(B0, wprep + OFF_D3, db[3], F1,
                                                   32, 32, 64, 64, 2, 0);
    tconv_s2<<<dim3(64, 1, B), 256>>>(F1, dw[4], db[4], F0, B0, 32, 16, 128, 128);
    conv_mma_s1<<<dim3(64, 1, B), 256, MMA_SMEM>>>(B0, wprep + OFF_D5, db[5], out,
                                                   16, 16, 128, 128, 2, 1);
}

// round 6
// speedup vs baseline: 2.4055x; 1.3297x over previous
#include <cuda_runtime.h>
#include <cuda_bf16.h>
#include <math.h>

// ---------------- scratch ----------------
__device__ float g_f0[32u * 32 * 128 * 128];              // fp32 NCHW ping
__device__ float g_f1[32u * 32 * 128 * 128];              // fp32 NCHW pong
__device__ unsigned short g_bf[2u * 32 * 32 * 128 * 128]; // bf16 hi/lo planes [px][2C]
__device__ uint4 g_wprep[60480];
__device__ float g_S[4096];
__device__ float g_Sh[4096];
__device__ float g_Sw[4096];

__device__ __forceinline__ float activate(float v, int act) {
    switch (act) {
        case 1: return v > 0.f ? v : 0.2f * v;
        case 2: return v > 0.f ? v : 0.f;
        case 3: return fmaxf(v, 0.f) + log1pf(expf(-fabsf(v)));
        default: return v;
    }
}

__device__ __forceinline__ void split_bf16(float x, unsigned short& h, unsigned short& l) {
    h = __bfloat16_as_ushort(__float2bfloat16(x));
    float hf = __uint_as_float((unsigned)h << 16);
    l = __bfloat16_as_ushort(__float2bfloat16(x - hf));
}
__device__ __forceinline__ unsigned pack_us(unsigned short a, unsigned short b) {
    return ((unsigned)b << 16) | (unsigned)a;
}
__device__ __forceinline__ unsigned pack2_bf16(float e_lo, float e_hi) {
    return ((unsigned)__bfloat16_as_ushort(__float2bfloat16(e_hi)) << 16)
         | (unsigned)__bfloat16_as_ushort(__float2bfloat16(e_lo));
}

__device__ __forceinline__ void cp_async4(void* sdst, const void* gsrc, bool pred) {
    unsigned saddr = (unsigned)__cvta_generic_to_shared(sdst);
    int sz = pred ? 4 : 0;
    asm volatile("cp.async.ca.shared.global [%0], [%1], 4, %2;\n"
                 :: "r"(saddr), "l"(gsrc), "r"(sz));
}
__device__ __forceinline__ void cp_async16(void* sdst, const void* gsrc, bool pred) {
    unsigned saddr = (unsigned)__cvta_generic_to_shared(sdst);
    int sz = pred ? 16 : 0;
    asm volatile("cp.async.cg.shared.global [%0], [%1], 16, %2;\n"
                 :: "r"(saddr), "l"(gsrc), "r"(sz));
}
__device__ __forceinline__ void cp_commit() { asm volatile("cp.async.commit_group;\n"); }
__device__ __forceinline__ void cp_wait0() { asm volatile("cp.async.wait_group 0;\n"); }

__device__ __forceinline__ void mma16816(float* d, const unsigned* a, unsigned b0, unsigned b1) {
    asm volatile("mma.sync.aligned.m16n8k16.row.col.f32.bf16.bf16.f32 "
                 "{%0,%1,%2,%3},{%4,%5,%6,%7},{%8,%9},{%0,%1,%2,%3};"
                 : "+f"(d[0]), "+f"(d[1]), "+f"(d[2]), "+f"(d[3])
                 : "r"(a[0]), "r"(a[1]), "r"(a[2]), "r"(a[3]), "r"(b0), "r"(b1));
}

// =====================================================================
// weight prep (3 layers/launch)
// =====================================================================
__global__ void prep_many(const float* __restrict__ w0, const float* __restrict__ w1,
                          const float* __restrict__ w2, uint4* __restrict__ dstb,
                          int off0, int off1, int off2,
                          int C0, int OC0, int C1, int OC1, int C2, int OC2)
{
    int layer = blockIdx.y;
    const float* w = layer == 0 ? w0 : layer == 1 ? w1 : w2;
    uint4* dst = dstb + (layer == 0 ? off0 : layer == 1 ? off1 : off2);
    int C = layer == 0 ? C0 : layer == 1 ? C1 : C2;
    int OC = layer == 0 ? OC0 : layer == 1 ? OC1 : OC2;
    int OCg = OC >> 3;
    int total = (C >> 4) * 9 * OCg * 32;
    int idx = blockIdx.x * 256 + threadIdx.x;
    if (idx >= total) return;
    int l = idx & 31;
    int q = idx >> 5;
    int og = q % OCg; q /= OCg;
    int t = q % 9;
    int kc = q / 9;
    int tg = l & 3, gg = l >> 2;
    int n = og * 8 + gg;
    float h[4], lo[4];
#pragma unroll
    for (int kk = 0; kk < 4; kk++) {
        int k = (kk < 2) ? (2 * tg + kk) : (2 * tg + 8 + (kk - 2));
        int ic = (kc << 4) + k;
        float e = w[((size_t)n * C + ic) * 9 + t];
        unsigned hb = (unsigned)__bfloat16_as_ushort(__float2bfloat16(e)) << 16;
        h[kk] = __uint_as_float(hb);
        lo[kk] = e - h[kk];
    }
    uint4 r;
    r.x = pack2_bf16(h[0], h[1]);
    r.y = pack2_bf16(h[2], h[3]);
    r.z = pack2_bf16(lo[0], lo[1]);
    r.w = pack2_bf16(lo[2], lo[3]);
    dst[idx] = r;
}

// =====================================================================
// tensor-core stride-1 3x3 SAME conv (bf16x3 split, fp32 accum).
// input: bf16 dual planes [px][2C]. output: fp32 NCHW.
// =====================================================================
#define SINW (324 * 12)
#define MMA_SW (9 * 4 * 32)
#define MMA_SMEM (2 * 2 * SINW * 4 + 2 * MMA_SW * 16)

__global__ void __launch_bounds__(256, 2) conv_mma_s1(
    const unsigned short* __restrict__ in, const uint4* __restrict__ wp,
    const float* __restrict__ bias, float* __restrict__ outp,
    int C, int OC, int H, int W, int act)
{
    const int KC = C >> 4;
    const int tilesX = W >> 4;
    const int x0 = (blockIdx.x % tilesX) << 4;
    const int y0 = (blockIdx.x / tilesX) << 4;
    const int oc0 = blockIdx.y << 5;
    const int b = blockIdx.z;
    const int OCg = OC >> 3;
    int nf = OCg - (oc0 >> 3); if (nf > 4) nf = 4;

    extern __shared__ __align__(16) unsigned char dsm[];
    unsigned* s_hi = (unsigned*)dsm;
    unsigned* s_lo = s_hi + 2 * SINW;
    uint4* s_w = (uint4*)(dsm + 4 * 4 * SINW);

    const unsigned short* inb = in + (size_t)b * H * W * 2 * C;
    const int tid = threadIdx.x, lane = tid & 31, wid = tid >> 5;
    const int g = lane >> 2, tg = lane & 3;

    float d[2][4][4];
#pragma unroll
    for (int i = 0; i < 2; i++)
#pragma unroll
        for (int j = 0; j < 4; j++)
#pragma unroll
            for (int r = 0; r < 4; r++) d[i][j][r] = 0.f;

    auto stage = [&](int buf, int kc) {
        unsigned* hi = s_hi + buf * SINW;
        unsigned* lo = s_lo + buf * SINW;
        for (int i = tid; i < 648; i += 256) {
            int sp = i >> 1, q = i & 1;
            int r = sp / 18, c = sp - r * 18;
            int iy = y0 - 1 + r, ix = x0 - 1 + c;
            bool p = (unsigned)iy < (unsigned)H && (unsigned)ix < (unsigned)W;
            const unsigned short* src = inb + ((size_t)iy * W + ix) * 2 * C + (kc << 4) + (q << 3);
            cp_async16(hi + sp * 12 + q * 4, src, p);
            cp_async16(lo + sp * 12 + q * 4, src + C, p);
        }
        uint4* sw = s_w + buf * MMA_SW;
        const uint4* wsrc = wp + (size_t)kc * 9 * OCg * 32;
        int tot = 9 * nf * 32;
        for (int i = tid; i < tot; i += 256) {
            int l = i & 31;
            int q = i >> 5;
            int ogl = q % nf;
            int t = q / nf;
            cp_async16(sw + (t * 4 + ogl) * 32 + l,
                       wsrc + ((size_t)t * OCg + (oc0 >> 3) + ogl) * 32 + l, true);
        }
    };

    auto compute = [&](int buf) {
        unsigned* hi = s_hi + buf * SINW;
        unsigned* lo = s_lo + buf * SINW;
        uint4* sw = s_w + buf * MMA_SW;
#pragma unroll
        for (int t = 0; t < 9; t++) {
            const int dy = t / 3, dx = t - 3 * (t / 3);
            unsigned ah[2][4], al[2][4];
#pragma unroll
            for (int i = 0; i < 2; i++) {
                int sp0 = (2 * wid + i + dy) * 18 + g + dx;
                const unsigned* h0 = hi + sp0 * 12;
                const unsigned* l0 = lo + sp0 * 12;
                ah[i][0] = h0[tg];       ah[i][1] = h0[96 + tg];
                ah[i][2] = h0[tg + 4];   ah[i][3] = h0[96 + tg + 4];
                al[i][0] = l0[tg];       al[i][1] = l0[96 + tg];
                al[i][2] = l0[tg + 4];   al[i][3] = l0[96 + tg + 4];
            }
            for (int j = 0; j < nf; j++) {
                uint4 bw = sw[(t * 4 + j) * 32 + lane];
#pragma unroll
                for (int i = 0; i < 2; i++) {
                    mma16816(d[i][j], ah[i], bw.x, bw.y);
                    mma16816(d[i][j], al[i], bw.x, bw.y);
                    mma16816(d[i][j], ah[i], bw.z, bw.w);
                }
            }
        }
    };

    stage(0, 0);
    cp_commit();
    for (int kc = 0; kc < KC; kc++) {
        int buf = kc & 1;
        cp_wait0();
        __syncthreads();
        if (kc + 1 < KC) stage(buf ^ 1, kc + 1);
        cp_commit();
        compute(buf);
    }

    // fp32 NCHW epilogue: rows(x)=g/g+8, cols(oc)=8j+2tg(+1); y=y0+2*wid+i
#pragma unroll
    for (int i = 0; i < 2; i++) {
        int y = y0 + 2 * wid + i;
        for (int j = 0; j < nf; j++) {
            int oc = oc0 + 8 * j + 2 * tg;
            float b0 = bias[oc], b1 = bias[oc + 1];
            size_t base0 = (((size_t)b * OC + oc) * H + y) * W + x0;
            size_t base1 = base0 + (size_t)H * W;
            outp[base0 + g]     = activate(d[i][j][0] + b0, act);
            outp[base1 + g]     = activate(d[i][j][1] + b1, act);
            outp[base0 + g + 8] = activate(d[i][j][2] + b0, act);
            outp[base1 + g + 8] = activate(d[i][j][3] + b1, act);
        }
    }
}

// bf16 dual-plane store of 8 contiguous oc
__device__ __forceinline__ void store_bf8(unsigned short* bout, size_t px, int OC,
                                          int ocbase, const float* v)
{
    unsigned short h[8], l[8];
#pragma unroll
    for (int o = 0; o < 8; o++) split_bf16(v[o], h[o], l[o]);
    unsigned short* bb = bout + px * 2 * OC + ocbase;
    uint4 H, L;
    H.x = pack_us(h[0], h[1]); H.y = pack_us(h[2], h[3]);
    H.z = pack_us(h[4], h[5]); H.w = pack_us(h[6], h[7]);
    L.x = pack_us(l[0], l[1]); L.y = pack_us(l[2], l[3]);
    L.z = pack_us(l[4], l[5]); L.w = pack_us(l[6], l[7]);
    *(uint4*)bb = H;
    *(uint4*)(bb + OC) = L;
}

// =====================================================================
// e0: fp32 NCHW in (C=3) -> bf16 planes. block 32x16 tile x 32 oc.
// =====================================================================
__global__ void __launch_bounds__(256, 2) conv_e0(
    const float* __restrict__ in, const float* __restrict__ wgt,
    const float* __restrict__ bias, unsigned short* __restrict__ bout,
    int C, int OC, int H, int W, int act)
{
    constexpr int NT = 256;
    constexpr int ICB = 4;
    constexpr int SROW = 34;
    constexpr int SIN = 18 * SROW;

    const int tilesX = W >> 5;
    const int x0 = (blockIdx.x % tilesX) << 5;
    const int y0 = (blockIdx.x / tilesX) << 4;
    const int oc0 = blockIdx.y * 32;
    const int b = blockIdx.z;

    __shared__ __align__(16) float s_in[2][ICB][SIN];
    __shared__ __align__(16) float s_w[2][ICB][32 * 12];

    const int tid = threadIdx.x;
    const int g = tid >> 6;
    const int sp = tid & 63;
    const int ty = sp >> 3, tx = sp & 7;

    float acc[8][2][4];
#pragma unroll
    for (int o = 0; o < 8; o++)
#pragma unroll
        for (int dy = 0; dy < 2; dy++)
#pragma unroll
            for (int dx = 0; dx < 4; dx++) acc[o][dy][dx] = 0.f;

    const float* inb = in + (size_t)b * C * H * W;
    const float* wb = wgt + (size_t)oc0 * C * 9;

    auto stage_copy = [&](int buf, int ic0, int cnt) {
        const float* ins = inb + (size_t)ic0 * H * W;
        for (int i = tid; i < cnt * SIN; i += NT) {
            int ch = i / SIN, r2 = i - ch * SIN;
            int r = r2 / SROW, c2 = r2 - r * SROW;
            int iy = y0 - 1 + r, ix = x0 - 1 + c2;
            bool p = (unsigned)iy < (unsigned)H && (unsigned)ix < (unsigned)W;
            cp_async4(&s_in[buf][ch][r2], ins + (size_t)ch * H * W + (size_t)iy * W + ix, p);
        }
        for (int i = tid; i < cnt * 32 * 9; i += NT) {
            int ch = i / (32 * 9), r2 = i - ch * (32 * 9);
            int o = r2 / 9, j2 = r2 - o * 9;
            cp_async4(&s_w[buf][ch][o * 12 + j2],
                      wb + ((size_t)o * C + ic0 + ch) * 9 + j2, true);
        }
    };

    const int sbase = (2 * ty) * SROW + 4 * tx;

    auto compute_ch = [&](int buf, int ch) {
        float rr[4][6];
        const float* si = &s_in[buf][ch][sbase];
#pragma unroll
        for (int r = 0; r < 4; r++) {
            const float2* p = (const float2*)(si + r * SROW);
            float2 a = p[0], b2 = p[1], c2 = p[2];
            rr[r][0] = a.x; rr[r][1] = a.y; rr[r][2] = b2.x;
            rr[r][3] = b2.y; rr[r][4] = c2.x; rr[r][5] = c2.y;
        }
#pragma unroll
        for (int o = 0; o < 8; o++) {
            const float4* wp = (const float4*)&s_w[buf][ch][(g * 8 + o) * 12];
            float4 wa = wp[0];
            float4 wc = wp[1];
            float w8 = ((const float*)wp)[8];
#pragma unroll
            for (int dy = 0; dy < 2; dy++)
#pragma unroll
                for (int dx = 0; dx < 4; dx++) {
                    float s = acc[o][dy][dx];
                    s += wa.x * rr[dy + 0][dx + 0];
                    s += wa.y * rr[dy + 0][dx + 1];
                    s += wa.z * rr[dy + 0][dx + 2];
                    s += wa.w * rr[dy + 1][dx + 0];
                    s += wc.x * rr[dy + 1][dx + 1];
                    s += wc.y * rr[dy + 1][dx + 2];
                    s += wc.z * rr[dy + 2][dx + 0];
                    s += wc.w * rr[dy + 2][dx + 1];
                    s += w8   * rr[dy + 2][dx + 2];
                    acc[o][dy][dx] = s;
                }
        }
    };

    const int nst = (C + ICB - 1) / ICB;
    stage_copy(0, 0, C < ICB ? C : ICB);
    cp_commit();
    for (int s = 0; s < nst; s++) {
        int buf = s & 1;
        cp_wait0();
        __syncthreads();
        int icn = (s + 1) * ICB;
        if (icn < C) {
            int cn = C - icn; if (cn > ICB) cn = ICB;
            stage_copy(buf ^ 1, icn, cn);
        }
        cp_commit();
        int cnt = C - s * ICB; if (cnt > ICB) cnt = ICB;
        for (int j = 0; j < cnt; j++) compute_ch(buf, j);
    }

    float bv[8];
#pragma unroll
    for (int o = 0; o < 8; o++) bv[o] = bias[oc0 + g * 8 + o];
    unsigned short* bo = bout + (size_t)b * H * W * 2 * OC;
#pragma unroll
    for (int dy = 0; dy < 2; dy++)
#pragma unroll
        for (int dx = 0; dx < 4; dx++) {
            int y = y0 + 2 * ty + dy, x = x0 + 4 * tx + dx;
            float v[8];
#pragma unroll
            for (int o = 0; o < 8; o++) v[o] = activate(acc[o][dy][dx] + bv[o], act);
            store_bf8(bo, (size_t)y * W + x, OC, oc0 + g * 8, v);
        }
}

// =====================================================================
// stride-2 3x3 SAME conv. fp32 NCHW in -> bf16 planes (mode 0) or
// fp32 NCHW (mode 1).
// =====================================================================
template <int OCB>
__global__ void __launch_bounds__(64 * (OCB / 8), 512 / (64 * (OCB / 8))) conv_s2(
    const float* __restrict__ in, const float* __restrict__ wgt,
    const float* __restrict__ bias, unsigned short* __restrict__ bout,
    float* __restrict__ fout, int C, int OC, int Hout, int Wout, int act, int mode)
{
    constexpr int NT = 64 * (OCB / 8);
    constexpr int ICB = 4;
    constexpr int SIN = 33 * 33;

    const int Hin = Hout * 2, Win = Wout * 2;
    const int tilesX = Wout >> 4;
    const int x0 = (blockIdx.x % tilesX) << 4;
    const int y0 = (blockIdx.x / tilesX) << 4;
    const int oc0 = blockIdx.y * OCB;
    const int b = blockIdx.z;

    __shared__ __align__(16) float s_in[2][ICB][SIN + 1];
    __shared__ __align__(16) float s_w[2][ICB][OCB * 12];

    const int tid = threadIdx.x;
    const int g = tid >> 6;
    const int sp = tid & 63;
    const int ty = sp >> 3, tx = sp & 7;

    float acc[8][4];
#pragma unroll
    for (int o = 0; o < 8; o++)
#pragma unroll
        for (int p = 0; p < 4; p++) acc[o][p] = 0.f;

    const float* inb = in + (size_t)b * C * Hin * Win;
    const float* wb = wgt + (size_t)oc0 * C * 9;

    auto stage_copy = [&](int buf, int ic0, int cnt) {
        const float* ins = inb + (size_t)ic0 * Hin * Win;
        for (int i = tid; i < cnt * SIN; i += NT) {
            int ch = i / SIN, r2 = i - ch * SIN;
            int r = r2 / 33, c2 = r2 - r * 33;
            int iy = 2 * y0 + r, ix = 2 * x0 + c2;
            bool p = iy < Hin && ix < Win;
            cp_async4(&s_in[buf][ch][r2], ins + (size_t)ch * Hin * Win + (size_t)iy * Win + ix, p);
        }
        for (int i = tid; i < cnt * OCB * 9; i += NT) {
            int ch = i / (OCB * 9), r2 = i - ch * (OCB * 9);
            int o = r2 / 9, j2 = r2 - o * 9;
            cp_async4(&s_w[buf][ch][o * 12 + j2],
                      wb + ((size_t)o * C + ic0 + ch) * 9 + j2, true);
        }
    };

    auto compute_ch = [&](int buf, int ch) {
        float rr[5][5];
#pragma unroll
        for (int r = 0; r < 5; r++)
#pragma unroll
            for (int c = 0; c < 5; c++)
                rr[r][c] = s_in[buf][ch][(4 * ty + r) * 33 + 4 * tx + c];
#pragma unroll
        for (int o = 0; o < 8; o++) {
            const float4* wp = (const float4*)&s_w[buf][ch][(g * 8 + o) * 12];
            float4 wa = wp[0];
            float4 wc = wp[1];
            float w8 = ((const float*)wp)[8];
#pragma unroll
            for (int dy = 0; dy < 2; dy++)
#pragma unroll
                for (int dx = 0; dx < 2; dx++) {
                    float s = acc[o][dy * 2 + dx];
                    s += wa.x * rr[2 * dy + 0][2 * dx + 0];
                    s += wa.y * rr[2 * dy + 0][2 * dx + 1];
                    s += wa.z * rr[2 * dy + 0][2 * dx + 2];
                    s += wa.w * rr[2 * dy + 1][2 * dx + 0];
                    s += wc.x * rr[2 * dy + 1][2 * dx + 1];
                    s += wc.y * rr[2 * dy + 1][2 * dx + 2];
                    s += wc.z * rr[2 * dy + 2][2 * dx + 0];
                    s += wc.w * rr[2 * dy + 2][2 * dx + 1];
                    s += w8   * rr[2 * dy + 2][2 * dx + 2];
                    acc[o][dy * 2 + dx] = s;
                }
        }
    };

    const int nst = (C + ICB - 1) / ICB;
    stage_copy(0, 0, C < ICB ? C : ICB);
    cp_commit();
    for (int s = 0; s < nst; s++) {
        int buf = s & 1;
        cp_wait0();
        __syncthreads();
        int icn = (s + 1) * ICB;
        if (icn < C) {
            int cn = C - icn; if (cn > ICB) cn = ICB;
            stage_copy(buf ^ 1, icn, cn);
        }
        cp_commit();
        int cnt = C - s * ICB; if (cnt > ICB) cnt = ICB;
        if (cnt == ICB) {
#pragma unroll
            for (int j = 0; j < ICB; j++) compute_ch(buf, j);
        } else {
            for (int j = 0; j < cnt; j++) compute_ch(buf, j);
        }
    }

    float bv[8];
#pragma unroll
    for (int o = 0; o < 8; o++) bv[o] = bias[oc0 + g * 8 + o];
    if (mode == 0) {
        unsigned short* bo = bout + (size_t)b * Hout * Wout * 2 * OC;
#pragma unroll
        for (int dy = 0; dy < 2; dy++)
#pragma unroll
            for (int dx = 0; dx < 2; dx++) {
                int y = y0 + 2 * ty + dy, x = x0 + 2 * tx + dx;
                float v[8];
#pragma unroll
                for (int o = 0; o < 8; o++) v[o] = activate(acc[o][dy * 2 + dx] + bv[o], act);
                store_bf8(bo, (size_t)y * Wout + x, OC, oc0 + g * 8, v);
            }
    } else {
#pragma unroll
        for (int o = 0; o < 8; o++) {
            int oc = oc0 + g * 8 + o;
            float* ob = fout + (((size_t)b * OC + oc) * Hout + y0) * (size_t)Wout + x0;
#pragma unroll
            for (int dy = 0; dy < 2; dy++)
#pragma unroll
                for (int dx = 0; dx < 2; dx++)
                    ob[(size_t)(2 * ty + dy) * Wout + 2 * tx + dx] =
                        activate(acc[o][dy * 2 + dx] + bv[o], act);
        }
    }
}

// =====================================================================
// transposed conv 3x3 stride-2 SAME (pad_a=2). fp32 NCHW in -> bf16. relu.
// =====================================================================
__global__ void __launch_bounds__(256, 3) tconv_s2(
    const float* __restrict__ in, const float* __restrict__ wgt,
    const float* __restrict__ bias, unsigned short* __restrict__ bout,
    int C, int OC, int Hout, int Wout)
{
    constexpr int NT = 256;
    constexpr int ICB = 4;
    constexpr int SIN = 9 * 9;

    const int Hin = Hout >> 1, Win = Wout >> 1;
    const int tilesX = Wout >> 4;
    const int x0 = (blockIdx.x % tilesX) << 4;
    const int y0 = (blockIdx.x / tilesX) << 4;
    const int oc0 = blockIdx.y * 16;
    const int b = blockIdx.z;
    const int Y0 = y0 >> 1, X0 = x0 >> 1;

    __shared__ __align__(16) float s_in[2][ICB][SIN + 3];
    __shared__ __align__(16) float s_w[2][ICB][16 * 12];

    const int tid = threadIdx.x;
    const int g = tid >> 6;
    const int sp = tid & 63;
    const int ty = sp >> 3, tx = sp & 7;

    float acc[4][4];
#pragma unroll
    for (int o = 0; o < 4; o++)
#pragma unroll
        for (int p = 0; p < 4; p++) acc[o][p] = 0.f;

    const float* inb = in + (size_t)b * C * Hin * Win;
    const float* wb = wgt + (size_t)oc0 * C * 9;

    auto stage_copy = [&](int buf, int ic0, int cnt) {
        const float* ins = inb + (size_t)ic0 * Hin * Win;
        for (int i = tid; i < cnt * SIN; i += NT) {
            int ch = i / SIN, r2 = i - ch * SIN;
            int r = r2 / 9, c2 = r2 - r * 9;
            int iy = Y0 - 1 + r, ix = X0 - 1 + c2;
            bool p = (unsigned)iy < (unsigned)Hin && (unsigned)ix < (unsigned)Win;
            cp_async4(&s_in[buf][ch][r2], ins + (size_t)ch * Hin * Win + (size_t)iy * Win + ix, p);
        }
        for (int i = tid; i < cnt * 16 * 9; i += NT) {
            int ch = i / (16 * 9), r2 = i - ch * (16 * 9);
            int o = r2 / 9, j2 = r2 - o * 9;
            cp_async4(&s_w[buf][ch][o * 12 + j2],
                      wb + ((size_t)o * C + ic0 + ch) * 9 + j2, true);
        }
    };

    auto compute_ch = [&](int buf, int ch) {
        const float* si = s_in[buf][ch];
        float r00 = si[ty * 9 + tx];
        float r01 = si[ty * 9 + tx + 1];
        float r10 = si[(ty + 1) * 9 + tx];
        float r11 = si[(ty + 1) * 9 + tx + 1];
#pragma unroll
        for (int o = 0; o < 4; o++) {
            const float4* wp = (const float4*)&s_w[buf][ch][(g * 4 + o) * 12];
            float4 wa = wp[0];
            float4 wc = wp[1];
            float w8 = ((const float*)wp)[8];
            acc[o][0] += wa.x * r00 + wa.z * r01 + wc.z * r10 + w8 * r11;
            acc[o][1] += wa.y * r01 + wc.w * r11;
            acc[o][2] += wa.w * r10 + wc.y * r11;
            acc[o][3] += wc.x * r11;
        }
    };

    const int nst = (C + ICB - 1) / ICB;
    stage_copy(0, 0, C < ICB ? C : ICB);
    cp_commit();
    for (int s = 0; s < nst; s++) {
        int buf = s & 1;
        cp_wait0();
        __syncthreads();
        int icn = (s + 1) * ICB;
        if (icn < C) {
            int cn = C - icn; if (cn > ICB) cn = ICB;
            stage_copy(buf ^ 1, icn, cn);
        }
        cp_commit();
        int cnt = C - s * ICB; if (cnt > ICB) cnt = ICB;
        if (cnt == ICB) {
#pragma unroll
            for (int j = 0; j < ICB; j++) compute_ch(buf, j);
        } else {
            for (int j = 0; j < cnt; j++) compute_ch(buf, j);
        }
    }

    float bv[4];
#pragma unroll
    for (int o = 0; o < 4; o++) bv[o] = bias[oc0 + g * 4 + o];
    unsigned short* bo = bout + (size_t)b * Hout * Wout * 2 * OC;
#pragma unroll
    for (int dy = 0; dy < 2; dy++)
#pragma unroll
        for (int dx = 0; dx < 2; dx++) {
            int y = y0 + 2 * ty + dy, x = x0 + 2 * tx + dx;
            size_t px = (size_t)y * Wout + x;
            float v[4];
#pragma unroll
            for (int o = 0; o < 4; o++) {
                float t = acc[o][dy * 2 + dx] + bv[o];
                v[o] = t > 0.f ? t : 0.f;
            }
            unsigned short h[4], l[4];
#pragma unroll
            for (int o = 0; o < 4; o++) split_bf16(v[o], h[o], l[o]);
            unsigned short* bb = bo + px * 2 * OC + oc0 + g * 4;
            *(uint2*)bb = make_uint2(pack_us(h[0], h[1]), pack_us(h[2], h[3]));
            *(uint2*)(bb + OC) = make_uint2(pack_us(l[0], l[1]), pack_us(l[2], l[3]));
        }
}

// ---------------- keypoint bottleneck (fp32 NCHW) ----------------
__global__ void bn_stats(const float* __restrict__ R, float* __restrict__ S,
                         float* __restrict__ Sh, float* __restrict__ Sw)
{
    int bk = blockIdx.x;
    int t = threadIdx.x;
    float v = R[(size_t)bk * 256 + t];
    float a = v;
    float bsum = v * (float)(t >> 4);
    float c = v * (float)(t & 15);
#pragma unroll
    for (int off = 16; off > 0; off >>= 1) {
        a += __shfl_down_sync(0xffffffffu, a, off);
        bsum += __shfl_down_sync(0xffffffffu, bsum, off);
        c += __shfl_down_sync(0xffffffffu, c, off);
    }
    __shared__ float sa[8], sb[8], sc[8];
    int wid = t >> 5;
    if ((t & 31) == 0) { sa[wid] = a; sb[wid] = bsum; sc[wid] = c; }
    __syncthreads();
    if (t == 0) {
        float ta = 0.f, tb = 0.f, tc = 0.f;
        for (int i = 0; i < 8; i++) { ta += sa[i]; tb += sb[i]; tc += sc[i]; }
        S[bk] = ta; Sh[bk] = tb; Sw[bk] = tc;
    }
}

__global__ void bn_maps(const float* __restrict__ S, const float* __restrict__ Sh,
                        const float* __restrict__ Sw, float* __restrict__ maps)
{
    int bk = blockIdx.x;
    int b = bk >> 7;
    float s = S[bk];
    float denom = S[(b << 7) | 127];
    float mu = s * (1.f / 256.f);
    float inv = 1.f / denom;
    float c0 = Sh[bk] * inv;
    float c1 = Sw[bk] * inv;
    int t = threadIdx.x;
    float h = (float)(t >> 4), w = (float)(t & 15);
    float dh = h - c0, dw = w - c1;
    maps[(size_t)bk * 256 + t] = mu * expf(-0.5f * (dh * dh + dw * dw));
}

// ---------------- launch ----------------
extern "C" void kernel_launch(void* const* d_in, const int* in_sizes, int n_in,
                              void* d_out, int out_size)
{
    (void)in_sizes; (void)n_in; (void)out_size;
    const float* x = (const float*)d_in[0];
    const float* ew[7]; const float* eb[7];
    for (int j = 0; j < 7; j++) {
        ew[j] = (const float*)d_in[1 + 2 * j];
        eb[j] = (const float*)d_in[2 + 2 * j];
    }
    const float* dw[6]; const float* db[6];
    for (int j = 0; j < 6; j++) {
        dw[j] = (const float*)d_in[15 + 2 * j];
        db[j] = (const float*)d_in[16 + 2 * j];
    }
    float* out = (float*)d_out;

    float *F0, *F1, *S, *Sh, *Sw;
    unsigned short* B0;
    uint4* wprep;
    cudaGetSymbolAddress((void**)&F0, g_f0);
    cudaGetSymbolAddress((void**)&F1, g_f1);
    cudaGetSymbolAddress((void**)&B0, g_bf);
    cudaGetSymbolAddress((void**)&wprep, g_wprep);
    cudaGetSymbolAddress((void**)&S, g_S);
    cudaGetSymbolAddress((void**)&Sh, g_Sh);
    cudaGetSymbolAddress((void**)&Sw, g_Sw);

    static bool attr_set = false;
    if (!attr_set) {
        cudaFuncSetAttribute(conv_mma_s1, cudaFuncAttributeMaxDynamicSharedMemorySize, MMA_SMEM);
        attr_set = true;
    }

    const int B = 32;
    const int OFF_E1 = 0, OFF_E3 = 2304, OFF_E5 = 11520;
    const int OFF_D1 = 48384, OFF_D3 = 57600, OFF_D5 = 59904;

    // 1: encoder weight prep
    prep_many<<<dim3(144, 3, 1), 256>>>(ew[1], ew[3], ew[5], wprep,
                                        OFF_E1, OFF_E3, OFF_E5, 32, 32, 64, 64, 128, 128);
    // 2: decoder weight prep
    prep_many<<<dim3(36, 3, 1), 256>>>(dw[1], dw[3], dw[5], wprep,
                                       OFF_D1, OFF_D3, OFF_D5, 64, 64, 32, 32, 16, 16);
    // 3: e0 (NCHW fp32 -> bf16 planes)
    conv_e0<<<dim3(32, 1, B), 256>>>(x, ew[0], eb[0], B0, 3, 32, 128, 128, 0);
    // 4: e1 mma (bf16 -> NCHW fp32)
    conv_mma_s1<<<dim3(64, 1, B), 256, MMA_SMEM>>>(B0, wprep + OFF_E1, eb[1], F0,
                                                   32, 32, 128, 128, 0);
    // 5: e2 s2 (NCHW -> bf16)
    conv_s2<32><<<dim3(16, 2, B), 256>>>(F0, ew[2], eb[2], B0, nullptr, 32, 64, 64, 64, 1, 0);
    // 6: e3 mma  <-- profiled launch
    conv_mma_s1<<<dim3(16, 2, B), 256, MMA_SMEM>>>(B0, wprep + OFF_E3, eb[3], F0,
                                                   64, 64, 64, 64, 1);
    conv_s2<32><<<dim3(4, 4, B), 256>>>(F0, ew[4], eb[4], B0, nullptr, 64, 128, 32, 32, 1, 0);
    conv_mma_s1<<<dim3(4, 4, B), 256, MMA_SMEM>>>(B0, wprep + OFF_E5, eb[5], F0,
                                                  128, 128, 32, 32, 1);
    conv_s2<8><<<dim3(1, 16, B), 64>>>(F0, ew[6], eb[6], nullptr, F1, 128, 128, 16, 16, 3, 1);
    // ---- keypoint bottleneck (NCHW fp32) ----
    bn_stats<<<4096, 256>>>(F1, S, Sh, Sw);
    bn_maps<<<4096, 256>>>(S, Sh, Sw, F0);
    // ---- decoder ----
    tconv_s2<<<dim3(4, 4, B), 256>>>(F0, dw[0], db[0], B0, 128, 64, 32, 32);
    conv_mma_s1<<<dim3(4, 2, B), 256, MMA_SMEM>>>(B0, wprep + OFF_D1, db[1], F0,
                                                  64, 64, 32, 32, 2);
    tconv_s2<<<dim3(16, 2, B), 256>>>(F0, dw[2], db[2], B0, 64, 32, 64, 64);
    conv_mma_s1<<<dim3(16, 1, B), 256, MMA_SMEM>>>(B0, wprep + OFF_D3, db[3], F0,
                                                   32, 32, 64, 64, 2);
    tconv_s2<<<dim3(64, 1, B), 256>>>(F0, dw[4], db[4], B0, 32, 16, 128, 128);
    conv_mma_s1<<<dim3(64, 1, B), 256, MMA_SMEM>>>(B0, wprep + OFF_D5, db[5], out,
                                                   16, 16, 128, 128, 2);
}